// round 2
// baseline (speedup 1.0000x reference)
#include <cuda_runtime.h>
#include <cuda_bf16.h>
#include <math.h>

// ---------------- problem constants ----------------
#define D_H 256
#define D_S 552
#define NV  148
#define LT  128
#define NB_ 64          // batch
#define ST_ 800
#define MAXDEC 1000
#define G4 1024         // 4*D_H
#define M_ENC (LT*NB_)       // 8192
#define M_DEC (MAXDEC*NB_)   // 64000
#define STOP_OFF ((size_t)M_DEC * D_S)   // 35,328,000

// ---------------- device scratch (static allocation is the sanctioned path) ----------------
__device__ float g_TE[M_ENC * D_H];            //  8.4 MB  token embeddings
__device__ float g_XencG[M_ENC * G4];          // 33.5 MB  enc gate x-part  [t][gcol][b]
__device__ float g_Xd[M_DEC * D_H];            // 65.5 MB  dec pre-net out
__device__ float g_XdG[(size_t)M_DEC * G4];    //  262 MB  dec gate x-part  [t][gcol][b]
__device__ float g_H[(size_t)M_DEC * D_H];     // 65.5 MB  decoder h history [t][b][j]
__device__ float g_Hid[(size_t)M_DEC * D_H];   // 65.5 MB
__device__ float g_Sh[(size_t)M_DEC * D_H];    // 65.5 MB
__device__ float g_hbuf[2 * D_H * NB_];        // ping-pong h, col-major [j][b]
__device__ unsigned int g_bar;

// ---------------- init ----------------
__global__ void init_k() {
    int i = blockIdx.x * blockDim.x + threadIdx.x;
    if (i == 0) g_bar = 0u;
    if (i < 2 * D_H * NB_) g_hbuf[i] = 0.f;
}

// ---------------- embedding gather ----------------
__global__ void gather_emb(const int* __restrict__ tok, const float* __restrict__ emb,
                           float* __restrict__ te) {
    int r = blockIdx.x;            // 0..8191  (= t*64+b)
    int k = threadIdx.x;           // 0..255
    te[r * D_H + k] = emb[tok[r] * D_H + k];
}

// ---------------- generic tiled SGEMM: C = act(A[M,K] @ W[N,K]^T + bias0 + bias1) ----------------
// amode 0: plain A.   amode 1: A is S_true; row r valid iff 64 <= r < 51200 (else zero row).
// cmode 0: C[r*N+n].  cmode 1: C[(r/64)*64N + n*64 + (r%64)]  (per-timestep transpose).
__global__ void __launch_bounds__(256) sgemm(
    const float* __restrict__ A, const float* __restrict__ Wt,
    const float* __restrict__ bias0, const float* __restrict__ bias1,
    float* __restrict__ C, int M, int N, int K,
    int amode, int cmode, int dorelu)
{
    __shared__ __align__(16) float As[8][128];
    __shared__ __align__(16) float Ws[8][128];
    const int tid = threadIdx.x;
    const int bm = blockIdx.x * 128;
    const int bn = blockIdx.y * 128;
    const int rowt = (tid >> 4) << 3;
    const int colt = (tid & 15) << 3;
    const int la_r = tid >> 1;
    const int la_k = (tid & 1) << 2;

    float acc[8][8];
#pragma unroll
    for (int i = 0; i < 8; i++)
#pragma unroll
        for (int j = 0; j < 8; j++) acc[i][j] = 0.f;

    for (int k0 = 0; k0 < K; k0 += 8) {
        // A tile (128 rows x 8 k)
        float4 av;
        int ar = bm + la_r;
        if (amode == 1) {
            if (ar >= 64 && ar < 51200)
                av = *(const float4*)(A + (size_t)ar * K + k0 + la_k);
            else av = make_float4(0.f, 0.f, 0.f, 0.f);
        } else {
            av = *(const float4*)(A + (size_t)ar * K + k0 + la_k);
        }
        As[la_k + 0][la_r] = av.x; As[la_k + 1][la_r] = av.y;
        As[la_k + 2][la_r] = av.z; As[la_k + 3][la_r] = av.w;
        // W tile (128 n x 8 k), guard n
        int wn = bn + la_r;
        float4 wv = make_float4(0.f, 0.f, 0.f, 0.f);
        if (wn < N) wv = *(const float4*)(Wt + (size_t)wn * K + k0 + la_k);
        Ws[la_k + 0][la_r] = wv.x; Ws[la_k + 1][la_r] = wv.y;
        Ws[la_k + 2][la_r] = wv.z; Ws[la_k + 3][la_r] = wv.w;
        __syncthreads();
#pragma unroll
        for (int kk = 0; kk < 8; kk++) {
            float a0[4], a1[4], w0[4], w1[4];
            *(float4*)a0 = *(const float4*)&As[kk][rowt];
            *(float4*)a1 = *(const float4*)&As[kk][rowt + 4];
            *(float4*)w0 = *(const float4*)&Ws[kk][colt];
            *(float4*)w1 = *(const float4*)&Ws[kk][colt + 4];
#pragma unroll
            for (int i = 0; i < 4; i++) {
#pragma unroll
                for (int j = 0; j < 4; j++) {
                    acc[i][j]         += a0[i] * w0[j];
                    acc[i][j + 4]     += a0[i] * w1[j];
                    acc[i + 4][j]     += a1[i] * w0[j];
                    acc[i + 4][j + 4] += a1[i] * w1[j];
                }
            }
        }
        __syncthreads();
    }
#pragma unroll
    for (int j = 0; j < 8; j++) {
        int n = bn + colt + j;
        if (n >= N) continue;
        float bv = 0.f;
        if (bias0) bv += bias0[n];
        if (bias1) bv += bias1[n];
#pragma unroll
        for (int i = 0; i < 8; i++) {
            int r = bm + rowt + i;
            float v = acc[i][j] + bv;
            if (dorelu) v = fmaxf(v, 0.f);
            if (cmode == 0) C[(size_t)r * N + n] = v;
            else C[(size_t)(r >> 6) * (64 * (size_t)N) + (size_t)n * 64 + (r & 63)] = v;
        }
    }
}

// ---------------- persistent recurrent LSTM (encoder 128 steps + decoder 1000 steps) ----------------
__device__ __forceinline__ float sigmoidf_(float x) { return 1.f / (1.f + __expf(-x)); }

#define SEQ_NB 128
#define SEQ_NT 128

__global__ void __launch_bounds__(SEQ_NT, 1) lstm_seq(
    const float* __restrict__ encWhh, const float* __restrict__ decWhh,
    const int* __restrict__ tlen)
{
    __shared__ __align__(16) float Wse[8][257];
    __shared__ __align__(16) float Wsd[8][257];
    __shared__ __align__(16) float part[4][8][64];

    const int tid = threadIdx.x;
    const int blk = blockIdx.x;
    const int j0 = blk * 2;                 // this CTA owns h-cols j0, j0+1

    // stage both recurrent weight slices (8 gate rows x 256) in smem, once
    for (int idx = tid; idx < 8 * 256; idx += SEQ_NT) {
        int gl = idx >> 8, k = idx & 255;
        int g = gl >> 1, l = gl & 1;
        int row = g * 256 + j0 + l;
        Wse[gl][k] = encWhh[row * 256 + k];
        Wsd[gl][k] = decWhh[row * 256 + k];
    }
    const int warp = tid >> 5, lane = tid & 31;
    const int b0  = (lane & 15) * 4;        // 4 batch rows
    const int gl0 = (lane >> 4) * 4;        // 4 gate-local cols
    const int kbeg = warp * 64;             // K split across warps
    const int ub = tid & 63, ul = tid >> 6; // update mapping: (b, local col)
    const int uj = j0 + ul;
    float c_reg = 0.f;
    const int mylen = tlen[ub];
    __syncthreads();

    for (int s = 0; s < LT + MAXDEC; s++) {
        // wait for h_s published by all CTAs (monotonic counter; h_0 trivially ready)
        if (tid == 0) {
            unsigned int tgt = (unsigned int)(SEQ_NB * s);
            while (*(volatile unsigned int*)&g_bar < tgt) { }
        }
        __syncthreads();

        const int cur = s & 1, nxt = cur ^ 1;
        const bool enc = (s < LT);
        const float* hb = g_hbuf + cur * (D_H * NB_);
        const float (*Ws)[257] = enc ? Wse : Wsd;

        // partial gate GEMM: acc[4b][4gl] over this warp's k-slice
        float acc[4][4];
#pragma unroll
        for (int i = 0; i < 4; i++)
#pragma unroll
            for (int g = 0; g < 4; g++) acc[i][g] = 0.f;

#pragma unroll 8
        for (int k = kbeg; k < kbeg + 64; k++) {
            float4 h4 = __ldcg((const float4*)(hb + k * 64 + b0));
            float w0 = Ws[gl0 + 0][k], w1 = Ws[gl0 + 1][k];
            float w2 = Ws[gl0 + 2][k], w3 = Ws[gl0 + 3][k];
            acc[0][0] += h4.x * w0; acc[1][0] += h4.y * w0; acc[2][0] += h4.z * w0; acc[3][0] += h4.w * w0;
            acc[0][1] += h4.x * w1; acc[1][1] += h4.y * w1; acc[2][1] += h4.z * w1; acc[3][1] += h4.w * w1;
            acc[0][2] += h4.x * w2; acc[1][2] += h4.y * w2; acc[2][2] += h4.z * w2; acc[3][2] += h4.w * w2;
            acc[0][3] += h4.x * w3; acc[1][3] += h4.y * w3; acc[2][3] += h4.z * w3; acc[3][3] += h4.w * w3;
        }
#pragma unroll
        for (int g = 0; g < 4; g++)
            *(float4*)&part[warp][gl0 + g][b0] =
                make_float4(acc[0][g], acc[1][g], acc[2][g], acc[3][g]);
        __syncthreads();

        // reduce across warps + x-part, then gate nonlinearity + state update
        const float* XG = enc ? (g_XencG + (size_t)s * (G4 * NB_))
                              : (g_XdG  + (size_t)(s - LT) * (G4 * NB_));
        float gv[4];
#pragma unroll
        for (int g = 0; g < 4; g++) {
            int gl = g * 2 + ul;
            float v = part[0][gl][ub] + part[1][gl][ub] + part[2][gl][ub] + part[3][gl][ub];
            v += XG[(g * 256 + uj) * 64 + ub];
            gv[g] = v;
        }
        if (s == LT)   // decoder init: c = enc_out (= current h)
            c_reg = __ldcg(hb + uj * 64 + ub);

        float iv = sigmoidf_(gv[0]);
        float fv = sigmoidf_(gv[1]);
        float gg = tanhf(gv[2]);
        float ov = sigmoidf_(gv[3]);
        float c2 = fv * c_reg + iv * gg;
        float h2 = ov * tanhf(c2);
        float hnew;
        if (enc) {
            bool m = (s < mylen);
            float hold = __ldcg(hb + uj * 64 + ub);
            c_reg = m ? c2 : c_reg;
            hnew  = m ? h2 : hold;
        } else {
            c_reg = c2;
            hnew  = h2;
            g_H[(size_t)(s - LT) * (NB_ * D_H) + ub * D_H + uj] = h2;
        }
        g_hbuf[nxt * (D_H * NB_) + uj * 64 + ub] = hnew;

        __threadfence();
        __syncthreads();
        if (tid == 0) atomicAdd(&g_bar, 1u);
    }
}

// ---------------- stop projection: out[r] = dot(Sh[r], w) + b ----------------
__global__ void stop_k(const float* __restrict__ sh, const float* __restrict__ w,
                       const float* __restrict__ b, float* __restrict__ out) {
    int row = blockIdx.x * 8 + (threadIdx.x >> 5);
    int lane = threadIdx.x & 31;
    const float* s = sh + (size_t)row * D_H;
    float acc = 0.f;
#pragma unroll
    for (int k = lane; k < D_H; k += 32) acc += s[k] * w[k];
#pragma unroll
    for (int o = 16; o; o >>= 1) acc += __shfl_down_sync(0xffffffffu, acc, o);
    if (lane == 0) out[row] = acc + b[0];
}

// ---------------- launch ----------------
extern "C" void kernel_launch(void* const* d_in, const int* in_sizes, int n_in,
                              void* d_out, int out_size) {
    const int*   token_pad     = (const int*)  d_in[0];
    const int*   token_lengths = (const int*)  d_in[1];
    const float* S_true        = (const float*)d_in[2];
    const float* emb           = (const float*)d_in[3];
    const float* enc_Wih       = (const float*)d_in[4];
    const float* enc_Whh       = (const float*)d_in[5];
    const float* enc_bih       = (const float*)d_in[6];
    const float* enc_bhh       = (const float*)d_in[7];
    const float* dec_Wih       = (const float*)d_in[8];
    const float* dec_Whh       = (const float*)d_in[9];
    const float* dec_bih       = (const float*)d_in[10];
    const float* dec_bhh       = (const float*)d_in[11];
    const float* pre_W         = (const float*)d_in[12];
    const float* pre_b         = (const float*)d_in[13];
    const float* post_W1       = (const float*)d_in[14];
    const float* post_b1       = (const float*)d_in[15];
    const float* post_W2       = (const float*)d_in[16];
    const float* post_b2       = (const float*)d_in[17];
    const float* stop_W1       = (const float*)d_in[18];
    const float* stop_b1       = (const float*)d_in[19];
    const float* stop_W2       = (const float*)d_in[20];
    const float* stop_b2       = (const float*)d_in[21];
    float* out = (float*)d_out;

    float *pTE, *pXencG, *pXd, *pXdG, *pH, *pHid, *pSh;
    cudaGetSymbolAddress((void**)&pTE,    g_TE);
    cudaGetSymbolAddress((void**)&pXencG, g_XencG);
    cudaGetSymbolAddress((void**)&pXd,    g_Xd);
    cudaGetSymbolAddress((void**)&pXdG,   g_XdG);
    cudaGetSymbolAddress((void**)&pH,     g_H);
    cudaGetSymbolAddress((void**)&pHid,   g_Hid);
    cudaGetSymbolAddress((void**)&pSh,    g_Sh);

    // 0. reset barrier + h ping-pong
    init_k<<<128, 256>>>();
    // 1. token embeddings
    gather_emb<<<M_ENC, 256>>>(token_pad, emb, pTE);
    // 2. encoder gate x-part  (bias = bih+bhh), stored [t][gcol][b]
    sgemm<<<dim3(M_ENC / 128, G4 / 128), 256>>>(pTE, enc_Wih, enc_bih, enc_bhh,
                                                pXencG, M_ENC, G4, D_H, 0, 1, 0);
    // 3. decoder pre-net: Xd = S_in @ pre_W^T + pre_b  (S_in masking inside)
    sgemm<<<dim3(M_DEC / 128, D_H / 128), 256>>>(S_true, pre_W, pre_b, nullptr,
                                                 pXd, M_DEC, D_H, D_S, 1, 0, 0);
    // 4. decoder gate x-part, stored [t][gcol][b]
    sgemm<<<dim3(M_DEC / 128, G4 / 128), 256>>>(pXd, dec_Wih, dec_bih, dec_bhh,
                                                pXdG, M_DEC, G4, D_H, 0, 1, 0);
    // 5. sequential LSTM (persistent, 1128 steps)
    lstm_seq<<<SEQ_NB, SEQ_NT>>>(enc_Whh, dec_Whh, token_lengths);
    // 6. post-net
    sgemm<<<dim3(M_DEC / 128, D_H / 128), 256>>>(pH, post_W1, post_b1, nullptr,
                                                 pHid, M_DEC, D_H, D_H, 0, 0, 1);
    sgemm<<<dim3(M_DEC / 128, (D_S + 127) / 128), 256>>>(pHid, post_W2, post_b2, nullptr,
                                                         out, M_DEC, D_S, D_H, 0, 0, 0);
    // 7. stop branch
    sgemm<<<dim3(M_DEC / 128, D_H / 128), 256>>>(pH, stop_W1, stop_b1, nullptr,
                                                 pSh, M_DEC, D_H, D_H, 0, 0, 1);
    stop_k<<<M_DEC / 8, 256>>>(pSh, stop_W2, stop_b2, out + STOP_OFF);
}

// round 3
// speedup vs baseline: 1.2742x; 1.2742x over previous
#include <cuda_runtime.h>
#include <cuda_bf16.h>
#include <math.h>
#include <stdint.h>

// ---------------- problem constants ----------------
#define D_H 256
#define D_S 552
#define LT  128
#define NB_ 64
#define ST_ 800
#define MAXDEC 1000
#define G4 1024
#define M_ENC (LT*NB_)       // 8192
#define M_DEC (MAXDEC*NB_)   // 64000
#define STOP_OFF ((size_t)M_DEC * D_S)
#define KP_S 560             // 552 padded to x16
#define NP_W2 640            // 552 padded to x128 rows for B tile loads

// ---------------- device scratch ----------------
__device__ __align__(256) float g_TE[M_ENC * D_H];
__device__ __align__(256) float g_XencG[M_ENC * G4];
__device__ __align__(256) float g_Sr[(size_t)M_DEC * KP_S];      // 143 MB rounded+masked S_in
__device__ __align__(256) float g_Xd[(size_t)M_DEC * D_H];
__device__ __align__(256) float g_XdG[(size_t)M_DEC * G4];       // 262 MB
__device__ __align__(256) float g_H[(size_t)M_DEC * D_H];
__device__ __align__(256) float g_Hid[(size_t)M_DEC * D_H];
__device__ __align__(256) float g_Sh[(size_t)M_DEC * D_H];
__device__ __align__(256) float g_Wr[962560];                    // rounded weights, packed
__device__ float g_hbuf[2 * D_H * NB_];
__device__ unsigned int g_bar;

// weight scratch offsets (floats)
#define W_ENC   0
#define W_DEC   262144
#define W_PRE   524288      // [256][560]
#define W_POST1 667648      // [256][256]
#define W_POST2 733184      // [640][256]
#define W_STOP1 897024      // [256][256]

__device__ __forceinline__ float to_tf32(float x) {
    float r; asm("cvt.rna.tf32.f32 %0, %1;" : "=f"(r) : "f"(x)); return r;
}

// ---------------- init ----------------
__global__ void init_k() {
    int i = blockIdx.x * blockDim.x + threadIdx.x;
    if (i == 0) g_bar = 0u;
    if (i < 2 * D_H * NB_) g_hbuf[i] = 0.f;
}

// ---------------- rounding / padding kernels ----------------
// dst is [Rdst][Cp]; valid source region [Rsrc][C]; everything else 0.
__global__ void round_pad(const float* __restrict__ src, float* __restrict__ dst,
                          int Rsrc, int Rdst, int C, int Cp) {
    int idx = blockIdx.x * 256 + threadIdx.x;
    if (idx >= Rdst * Cp) return;
    int r = idx / Cp, c = idx - r * Cp;
    float v = (r < Rsrc && c < C) ? to_tf32(src[(size_t)r * C + c]) : 0.f;
    dst[idx] = v;
}

// S_in: rows r=t*64+b valid iff 64 <= r < 51200 (t in [1,800)); round + pad K to 560
__global__ void round_S(const float* __restrict__ S, float* __restrict__ dst) {
    size_t idx = (size_t)blockIdx.x * 256 + threadIdx.x;
    if (idx >= (size_t)M_DEC * KP_S) return;
    int r = (int)(idx / KP_S), c = (int)(idx - (size_t)r * KP_S);
    float v = 0.f;
    if (r >= 64 && r < 51200 && c < D_S) v = to_tf32(S[(size_t)r * D_S + c]);
    dst[idx] = v;
}

// ---------------- embedding gather (rounded) ----------------
__global__ void gather_emb(const int* __restrict__ tok, const float* __restrict__ emb,
                           float* __restrict__ te) {
    int r = blockIdx.x;
    int k = threadIdx.x;
    te[r * D_H + k] = to_tf32(emb[tok[r] * D_H + k]);
}

// ---------------- tf32 tensor-core GEMM ----------------
// C[M,N] = act(A[M,K] @ B[N,K]^T + bias0 + bias1)
// A rows = M (mult of 128), lda given; B rows padded >= ceil(N/128)*128, ldb given.
// K mult of 16; all operands pre-rounded to tf32.
// cmode 0: C[r*N+n]; cmode 1: C[(r>>6)*64N + n*64 + (r&63)]
#define BM 128
#define BN 128
#define BK 16
#define SL 20   // padded smem row length (floats)

__device__ __forceinline__ void cp16(uint32_t s, const void* g) {
    asm volatile("cp.async.cg.shared.global [%0], [%1], 16;" :: "r"(s), "l"(g));
}

__global__ void __launch_bounds__(256) gemm_tc(
    const float* __restrict__ A, int lda,
    const float* __restrict__ B, int ldb,
    const float* __restrict__ bias0, const float* __restrict__ bias1,
    float* __restrict__ C, int M, int N, int K,
    int cmode, int dorelu, int doround)
{
    __shared__ __align__(16) float As[2][BM * SL];
    __shared__ __align__(16) float Bs[2][BN * SL];

    const int tid  = threadIdx.x;
    const int bm   = blockIdx.x * BM;
    const int bn   = blockIdx.y * BN;
    const int warp = tid >> 5, lane = tid & 31;
    const int wm   = (warp & 3) * 32;    // warp m-offset (4 warps in m)
    const int wn   = (warp >> 2) * 64;   // warp n-offset (2 warps in n)
    const int grp  = lane >> 2;          // 0..7
    const int tig  = lane & 3;           // 0..3

    const uint32_t sA = (uint32_t)__cvta_generic_to_shared(&As[0][0]);
    const uint32_t sB = (uint32_t)__cvta_generic_to_shared(&Bs[0][0]);

    float acc[2][8][4];
#pragma unroll
    for (int i = 0; i < 2; i++)
#pragma unroll
        for (int j = 0; j < 8; j++)
#pragma unroll
            for (int e = 0; e < 4; e++) acc[i][j][e] = 0.f;

    const int T = K / BK;

    // issue tile 0
    {
#pragma unroll
        for (int i = 0; i < 2; i++) {
            int f = i * 256 + tid, row = f >> 2, seg = (f & 3) * 4;
            cp16(sA + (uint32_t)(row * SL + seg) * 4, A + (size_t)(bm + row) * lda + seg);
            cp16(sB + (uint32_t)(row * SL + seg) * 4, B + (size_t)(bn + row) * ldb + seg);
        }
        asm volatile("cp.async.commit_group;" ::: "memory");
    }

    for (int t = 0; t < T; t++) {
        asm volatile("cp.async.wait_group 0;" ::: "memory");
        __syncthreads();

        if (t + 1 < T) {
            int k0 = (t + 1) * BK;
            uint32_t boff = (uint32_t)(((t + 1) & 1) * BM * SL) * 4;
#pragma unroll
            for (int i = 0; i < 2; i++) {
                int f = i * 256 + tid, row = f >> 2, seg = (f & 3) * 4;
                cp16(sA + boff + (uint32_t)(row * SL + seg) * 4,
                     A + (size_t)(bm + row) * lda + k0 + seg);
                cp16(sB + boff + (uint32_t)(row * SL + seg) * 4,
                     B + (size_t)(bn + row) * ldb + k0 + seg);
            }
            asm volatile("cp.async.commit_group;" ::: "memory");
        }

        const uint32_t* as = reinterpret_cast<const uint32_t*>(&As[t & 1][0]);
        const uint32_t* bs = reinterpret_cast<const uint32_t*>(&Bs[t & 1][0]);

#pragma unroll
        for (int kk = 0; kk < BK; kk += 8) {
            uint32_t a[2][4], b[8][2];
            const int c0 = kk + tig;
#pragma unroll
            for (int mt = 0; mt < 2; mt++) {
                int r0 = wm + mt * 16 + grp;
                a[mt][0] = as[r0 * SL + c0];
                a[mt][1] = as[(r0 + 8) * SL + c0];
                a[mt][2] = as[r0 * SL + c0 + 4];
                a[mt][3] = as[(r0 + 8) * SL + c0 + 4];
            }
#pragma unroll
            for (int nt = 0; nt < 8; nt++) {
                int n0 = wn + nt * 8 + grp;
                b[nt][0] = bs[n0 * SL + c0];
                b[nt][1] = bs[n0 * SL + c0 + 4];
            }
#pragma unroll
            for (int mt = 0; mt < 2; mt++)
#pragma unroll
                for (int nt = 0; nt < 8; nt++) {
                    asm volatile(
                        "mma.sync.aligned.m16n8k8.row.col.f32.tf32.tf32.f32 "
                        "{%0,%1,%2,%3}, {%4,%5,%6,%7}, {%8,%9}, {%0,%1,%2,%3};"
                        : "+f"(acc[mt][nt][0]), "+f"(acc[mt][nt][1]),
                          "+f"(acc[mt][nt][2]), "+f"(acc[mt][nt][3])
                        : "r"(a[mt][0]), "r"(a[mt][1]), "r"(a[mt][2]), "r"(a[mt][3]),
                          "r"(b[nt][0]), "r"(b[nt][1]));
                }
        }
        __syncthreads();
    }

    // epilogue
#pragma unroll
    for (int nt = 0; nt < 8; nt++) {
#pragma unroll
        for (int e = 0; e < 4; e++) {
            int col = bn + wn + nt * 8 + tig * 2 + (e & 1);
            if (col >= N) continue;
            float bv = 0.f;
            if (bias0) bv += __ldg(bias0 + col);
            if (bias1) bv += __ldg(bias1 + col);
#pragma unroll
            for (int mt = 0; mt < 2; mt++) {
                int row = bm + wm + mt * 16 + grp + ((e >> 1) << 3);
                float v = acc[mt][nt][e] + bv;
                if (dorelu) v = fmaxf(v, 0.f);
                if (doround) v = to_tf32(v);
                if (cmode == 0)
                    C[(size_t)row * N + col] = v;
                else
                    C[(size_t)(row >> 6) * (64 * (size_t)N) + (size_t)col * 64 + (row & 63)] = v;
            }
        }
    }
}

// ---------------- persistent recurrent LSTM (unchanged structure, fp32) ----------------
__device__ __forceinline__ float sigmoidf_(float x) { return 1.f / (1.f + __expf(-x)); }

#define SEQ_NB 128
#define SEQ_NT 128

__global__ void __launch_bounds__(SEQ_NT, 1) lstm_seq(
    const float* __restrict__ encWhh, const float* __restrict__ decWhh,
    const int* __restrict__ tlen)
{
    __shared__ __align__(16) float Wse[8][257];
    __shared__ __align__(16) float Wsd[8][257];
    __shared__ __align__(16) float part[4][8][64];

    const int tid = threadIdx.x;
    const int blk = blockIdx.x;
    const int j0 = blk * 2;

    for (int idx = tid; idx < 8 * 256; idx += SEQ_NT) {
        int gl = idx >> 8, k = idx & 255;
        int g = gl >> 1, l = gl & 1;
        int row = g * 256 + j0 + l;
        Wse[gl][k] = encWhh[row * 256 + k];
        Wsd[gl][k] = decWhh[row * 256 + k];
    }
    const int warp = tid >> 5, lane = tid & 31;
    const int b0  = (lane & 15) * 4;
    const int gl0 = (lane >> 4) * 4;
    const int kbeg = warp * 64;
    const int ub = tid & 63, ul = tid >> 6;
    const int uj = j0 + ul;
    float c_reg = 0.f;
    const int mylen = tlen[ub];
    __syncthreads();

    for (int s = 0; s < LT + MAXDEC; s++) {
        if (tid == 0) {
            unsigned int tgt = (unsigned int)(SEQ_NB * s);
            while (*(volatile unsigned int*)&g_bar < tgt) { }
        }
        __syncthreads();

        const int cur = s & 1, nxt = cur ^ 1;
        const bool enc = (s < LT);
        const float* hb = g_hbuf + cur * (D_H * NB_);
        const float (*Ws)[257] = enc ? Wse : Wsd;

        float acc[4][4];
#pragma unroll
        for (int i = 0; i < 4; i++)
#pragma unroll
            for (int g = 0; g < 4; g++) acc[i][g] = 0.f;

#pragma unroll 8
        for (int k = kbeg; k < kbeg + 64; k++) {
            float4 h4 = __ldcg((const float4*)(hb + k * 64 + b0));
            float w0 = Ws[gl0 + 0][k], w1 = Ws[gl0 + 1][k];
            float w2 = Ws[gl0 + 2][k], w3 = Ws[gl0 + 3][k];
            acc[0][0] += h4.x * w0; acc[1][0] += h4.y * w0; acc[2][0] += h4.z * w0; acc[3][0] += h4.w * w0;
            acc[0][1] += h4.x * w1; acc[1][1] += h4.y * w1; acc[2][1] += h4.z * w1; acc[3][1] += h4.w * w1;
            acc[0][2] += h4.x * w2; acc[1][2] += h4.y * w2; acc[2][2] += h4.z * w2; acc[3][2] += h4.w * w2;
            acc[0][3] += h4.x * w3; acc[1][3] += h4.y * w3; acc[2][3] += h4.z * w3; acc[3][3] += h4.w * w3;
        }
#pragma unroll
        for (int g = 0; g < 4; g++)
            *(float4*)&part[warp][gl0 + g][b0] =
                make_float4(acc[0][g], acc[1][g], acc[2][g], acc[3][g]);
        __syncthreads();

        const float* XG = enc ? (g_XencG + (size_t)s * (G4 * NB_))
                              : (g_XdG  + (size_t)(s - LT) * ((size_t)G4 * NB_));
        float gv[4];
#pragma unroll
        for (int g = 0; g < 4; g++) {
            int gl = g * 2 + ul;
            float v = part[0][gl][ub] + part[1][gl][ub] + part[2][gl][ub] + part[3][gl][ub];
            v += XG[(g * 256 + uj) * 64 + ub];
            gv[g] = v;
        }
        if (s == LT)
            c_reg = __ldcg(hb + uj * 64 + ub);

        float iv = sigmoidf_(gv[0]);
        float fv = sigmoidf_(gv[1]);
        float gg = tanhf(gv[2]);
        float ov = sigmoidf_(gv[3]);
        float c2 = fv * c_reg + iv * gg;
        float h2 = ov * tanhf(c2);
        float hnew;
        if (enc) {
            bool m = (s < mylen);
            float hold = __ldcg(hb + uj * 64 + ub);
            c_reg = m ? c2 : c_reg;
            hnew  = m ? h2 : hold;
        } else {
            c_reg = c2;
            hnew  = h2;
            g_H[(size_t)(s - LT) * (NB_ * D_H) + ub * D_H + uj] = to_tf32(h2);
        }
        g_hbuf[nxt * (D_H * NB_) + uj * 64 + ub] = hnew;

        __threadfence();
        __syncthreads();
        if (tid == 0) atomicAdd(&g_bar, 1u);
    }
}

// ---------------- stop projection ----------------
__global__ void stop_k(const float* __restrict__ sh, const float* __restrict__ w,
                       const float* __restrict__ b, float* __restrict__ out) {
    int row = blockIdx.x * 8 + (threadIdx.x >> 5);
    int lane = threadIdx.x & 31;
    const float* s = sh + (size_t)row * D_H;
    float acc = 0.f;
#pragma unroll
    for (int k = lane; k < D_H; k += 32) acc += s[k] * w[k];
#pragma unroll
    for (int o = 16; o; o >>= 1) acc += __shfl_down_sync(0xffffffffu, acc, o);
    if (lane == 0) out[row] = acc + b[0];
}

// ---------------- launch ----------------
extern "C" void kernel_launch(void* const* d_in, const int* in_sizes, int n_in,
                              void* d_out, int out_size) {
    const int*   token_pad     = (const int*)  d_in[0];
    const int*   token_lengths = (const int*)  d_in[1];
    const float* S_true        = (const float*)d_in[2];
    const float* emb           = (const float*)d_in[3];
    const float* enc_Wih       = (const float*)d_in[4];
    const float* enc_Whh       = (const float*)d_in[5];
    const float* enc_bih       = (const float*)d_in[6];
    const float* enc_bhh       = (const float*)d_in[7];
    const float* dec_Wih       = (const float*)d_in[8];
    const float* dec_Whh       = (const float*)d_in[9];
    const float* dec_bih       = (const float*)d_in[10];
    const float* dec_bhh       = (const float*)d_in[11];
    const float* pre_W         = (const float*)d_in[12];
    const float* pre_b         = (const float*)d_in[13];
    const float* post_W1       = (const float*)d_in[14];
    const float* post_b1       = (const float*)d_in[15];
    const float* post_W2       = (const float*)d_in[16];
    const float* post_b2       = (const float*)d_in[17];
    const float* stop_W1       = (const float*)d_in[18];
    const float* stop_b1       = (const float*)d_in[19];
    const float* stop_W2       = (const float*)d_in[20];
    const float* stop_b2       = (const float*)d_in[21];
    float* out = (float*)d_out;

    float *pTE, *pXencG, *pSr, *pXd, *pXdG, *pH, *pHid, *pSh, *pWr;
    cudaGetSymbolAddress((void**)&pTE,    g_TE);
    cudaGetSymbolAddress((void**)&pXencG, g_XencG);
    cudaGetSymbolAddress((void**)&pSr,    g_Sr);
    cudaGetSymbolAddress((void**)&pXd,    g_Xd);
    cudaGetSymbolAddress((void**)&pXdG,   g_XdG);
    cudaGetSymbolAddress((void**)&pH,     g_H);
    cudaGetSymbolAddress((void**)&pHid,   g_Hid);
    cudaGetSymbolAddress((void**)&pSh,    g_Sh);
    cudaGetSymbolAddress((void**)&pWr,    g_Wr);

    init_k<<<128, 256>>>();

    // round weights into scratch
    round_pad<<<(1024*256+255)/256, 256>>>(enc_Wih, pWr + W_ENC,   1024, 1024, 256, 256);
    round_pad<<<(1024*256+255)/256, 256>>>(dec_Wih, pWr + W_DEC,   1024, 1024, 256, 256);
    round_pad<<<(256*KP_S+255)/256, 256>>>(pre_W,   pWr + W_PRE,   256,  256,  D_S, KP_S);
    round_pad<<<(256*256+255)/256,  256>>>(post_W1, pWr + W_POST1, 256,  256,  256, 256);
    round_pad<<<(NP_W2*256+255)/256,256>>>(post_W2, pWr + W_POST2, D_S,  NP_W2,256, 256);
    round_pad<<<(256*256+255)/256,  256>>>(stop_W1, pWr + W_STOP1, 256,  256,  256, 256);
    // round + mask + pad S_in
    {
        size_t n = (size_t)M_DEC * KP_S;
        round_S<<<(unsigned)((n + 255) / 256), 256>>>(S_true, pSr);
    }
    // token embeddings (rounded)
    gather_emb<<<M_ENC, 256>>>(token_pad, emb, pTE);

    // enc gate x-part: [8192,256] @ enc_Wih^T -> [t][gcol][b]
    gemm_tc<<<dim3(M_ENC/128, G4/128), 256>>>(pTE, 256, pWr + W_ENC, 256,
        enc_bih, enc_bhh, pXencG, M_ENC, G4, 256, 1, 0, 0);
    // pre-net: [64000,560] @ pre_W^T -> Xd (rounded)
    gemm_tc<<<dim3(M_DEC/128, D_H/128), 256>>>(pSr, KP_S, pWr + W_PRE, KP_S,
        pre_b, nullptr, pXd, M_DEC, D_H, KP_S, 0, 0, 1);
    // dec gate x-part
    gemm_tc<<<dim3(M_DEC/128, G4/128), 256>>>(pXd, 256, pWr + W_DEC, 256,
        dec_bih, dec_bhh, pXdG, M_DEC, G4, 256, 1, 0, 0);
    // sequential LSTM
    lstm_seq<<<SEQ_NB, SEQ_NT>>>(enc_Whh, dec_Whh, token_lengths);
    // post-net
    gemm_tc<<<dim3(M_DEC/128, D_H/128), 256>>>(pH, 256, pWr + W_POST1, 256,
        post_b1, nullptr, pHid, M_DEC, D_H, 256, 0, 1, 1);
    gemm_tc<<<dim3(M_DEC/128, (D_S+127)/128), 256>>>(pHid, 256, pWr + W_POST2, 256,
        post_b2, nullptr, out, M_DEC, D_S, 256, 0, 0, 0);
    // stop branch
    gemm_tc<<<dim3(M_DEC/128, D_H/128), 256>>>(pH, 256, pWr + W_STOP1, 256,
        stop_b1, nullptr, pSh, M_DEC, D_H, 256, 0, 1, 0);
    stop_k<<<M_DEC/8, 256>>>(pSh, stop_W2, stop_b2, out + STOP_OFF);
}

// round 4
// speedup vs baseline: 1.4333x; 1.1249x over previous
#include <cuda_runtime.h>
#include <cuda_bf16.h>
#include <math.h>
#include <stdint.h>

// ---------------- problem constants ----------------
#define D_H 256
#define D_S 552
#define LT  128
#define NB_ 64
#define MAXDEC 1000
#define G4 1024
#define M_ENC (LT*NB_)       // 8192
#define M_DEC (MAXDEC*NB_)   // 64000
#define STOP_OFF ((size_t)M_DEC * D_S)
#define KP_S 560             // 552 padded to x16

// ---------------- device scratch ----------------
__device__ __align__(256) float g_TE[M_ENC * D_H];
__device__ __align__(256) float g_XencG[M_ENC * G4];
__device__ __align__(256) float g_Xd[(size_t)M_DEC * D_H];
__device__ __align__(256) float g_XdG[(size_t)M_DEC * G4];       // 262 MB
__device__ __align__(256) float g_H[(size_t)M_DEC * D_H];
__device__ __align__(256) float g_Hid[(size_t)M_DEC * D_H];
__device__ __align__(256) float g_StopP[2 * M_DEC];
__device__ __align__(256) float g_Wr[962560];                    // rounded weights
__device__ __align__(256) float g_bcat[512];
__device__ float g_hbuf[2 * D_H * NB_];
__device__ unsigned int g_bar;

// weight scratch offsets (floats)
#define W_ENC   0
#define W_DEC   262144
#define W_PRE   524288      // [256][560]
#define W_P1S   667648      // [512][256]  post_W1 rows 0..255, stop_W1 rows 256..511
#define W_POST2 798720      // [640][256]

__device__ __forceinline__ float to_tf32(float x) {
    float r; asm("cvt.rna.tf32.f32 %0, %1;" : "=f"(r) : "f"(x)); return r;
}

// ---------------- init ----------------
__global__ void init_k() {
    int i = blockIdx.x * blockDim.x + threadIdx.x;
    if (i == 0) g_bar = 0u;
    if (i < 2 * D_H * NB_) g_hbuf[i] = 0.f;
}

__global__ void biascat_k(const float* __restrict__ b1, const float* __restrict__ b2) {
    int i = threadIdx.x + blockIdx.x * 256;
    if (i < 512) g_bcat[i] = (i < 256) ? b1[i] : b2[i - 256];
}

// dst is [Rdst][Cp]; valid source region [Rsrc][C]; everything else 0.
__global__ void round_pad(const float* __restrict__ src, float* __restrict__ dst,
                          int Rsrc, int Rdst, int C, int Cp) {
    int idx = blockIdx.x * 256 + threadIdx.x;
    if (idx >= Rdst * Cp) return;
    int r = idx / Cp, c = idx - r * Cp;
    float v = (r < Rsrc && c < C) ? to_tf32(src[(size_t)r * C + c]) : 0.f;
    dst[idx] = v;
}

// ---------------- embedding gather (rounded) ----------------
__global__ void gather_emb(const int* __restrict__ tok, const float* __restrict__ emb,
                           float* __restrict__ te) {
    int r = blockIdx.x;
    int k = threadIdx.x;
    te[r * D_H + k] = to_tf32(emb[tok[r] * D_H + k]);
}

// ---------------- tf32 tensor-core GEMM ----------------
// C = act(A[M,K] @ B[N,K]^T + bias).  A-loader masks rows outside [rowlo,rowhi)
// and cols >= kvalid (16B-granule aligned). RA: round A in-register (A not pre-rounded).
// cmode 0: C[r*N+n]; 1: timestep transpose; 2: fused Hid+stop.
#define BM 128
#define BN 128
#define BK 16
#define SL 20

__device__ __forceinline__ void cp16(uint32_t s, const void* g) {
    asm volatile("cp.async.cg.shared.global [%0], [%1], 16;" :: "r"(s), "l"(g));
}

template<int RA>
__global__ void __launch_bounds__(256) gemm_tc(
    const float* __restrict__ A, int lda, int rowlo, int rowhi, int kvalid,
    const float* __restrict__ B, int ldb,
    const float* __restrict__ bias0, const float* __restrict__ bias1,
    float* __restrict__ C, int M, int N, int K,
    int cmode, int dorelu, int doround,
    const float* __restrict__ w2, float* __restrict__ stopP)
{
    __shared__ __align__(16) float As[2][BM * SL];
    __shared__ __align__(16) float Bs[2][BN * SL];
    __shared__ float spart[2][BM];

    const int tid  = threadIdx.x;
    const int bm   = blockIdx.x * BM;
    const int bn   = blockIdx.y * BN;
    const int warp = tid >> 5, lane = tid & 31;
    const int wm   = (warp & 3) * 32;
    const int wn   = (warp >> 2) * 64;
    const int grp  = lane >> 2;
    const int tig  = lane & 3;

    float acc[2][8][4];
#pragma unroll
    for (int i = 0; i < 2; i++)
#pragma unroll
        for (int j = 0; j < 8; j++)
#pragma unroll
            for (int e = 0; e < 4; e++) acc[i][j][e] = 0.f;

    const int T = K / BK;
    const int lrow = tid >> 2, lseg = (tid & 3) * 4;   // 256 threads: rows 0..63? no:
    // 2 granule-passes per thread cover 128 rows x 16 cols.

    // loader lambda-ish macro
#define LOAD_TILE(t)                                                            \
    {                                                                           \
        int k0 = (t) * BK;                                                      \
        int buf = (t) & 1;                                                      \
        _Pragma("unroll")                                                       \
        for (int i = 0; i < 2; i++) {                                           \
            int f = i * 256 + tid, row = f >> 2, seg = (f & 3) * 4;             \
            int ar = bm + row, kk = k0 + seg;                                   \
            float* da = &As[buf][row * SL + seg];                               \
            if (ar >= rowlo && ar < rowhi && kk < kvalid)                       \
                cp16((uint32_t)__cvta_generic_to_shared(da),                    \
                     A + (size_t)ar * lda + kk);                                \
            else                                                                \
                *(float4*)da = make_float4(0.f, 0.f, 0.f, 0.f);                 \
            float* db = &Bs[buf][row * SL + seg];                               \
            cp16((uint32_t)__cvta_generic_to_shared(db),                        \
                 B + (size_t)(bn + row) * ldb + kk);                            \
        }                                                                       \
        asm volatile("cp.async.commit_group;" ::: "memory");                    \
    }

    LOAD_TILE(0);

    for (int t = 0; t < T; t++) {
        asm volatile("cp.async.wait_group 0;" ::: "memory");
        __syncthreads();
        if (t + 1 < T) LOAD_TILE(t + 1);

        const uint32_t* as = reinterpret_cast<const uint32_t*>(&As[t & 1][0]);
        const uint32_t* bs = reinterpret_cast<const uint32_t*>(&Bs[t & 1][0]);

#pragma unroll
        for (int kk = 0; kk < BK; kk += 8) {
            uint32_t a[2][4], b[8][2];
            const int c0 = kk + tig;
#pragma unroll
            for (int mt = 0; mt < 2; mt++) {
                int r0 = wm + mt * 16 + grp;
                a[mt][0] = as[r0 * SL + c0];
                a[mt][1] = as[(r0 + 8) * SL + c0];
                a[mt][2] = as[r0 * SL + c0 + 4];
                a[mt][3] = as[(r0 + 8) * SL + c0 + 4];
                if (RA) {
#pragma unroll
                    for (int q = 0; q < 4; q++)
                        a[mt][q] = __float_as_uint(to_tf32(__uint_as_float(a[mt][q])));
                }
            }
#pragma unroll
            for (int nt = 0; nt < 8; nt++) {
                int n0 = wn + nt * 8 + grp;
                b[nt][0] = bs[n0 * SL + c0];
                b[nt][1] = bs[n0 * SL + c0 + 4];
            }
#pragma unroll
            for (int mt = 0; mt < 2; mt++)
#pragma unroll
                for (int nt = 0; nt < 8; nt++) {
                    asm volatile(
                        "mma.sync.aligned.m16n8k8.row.col.f32.tf32.tf32.f32 "
                        "{%0,%1,%2,%3}, {%4,%5,%6,%7}, {%8,%9}, {%0,%1,%2,%3};"
                        : "+f"(acc[mt][nt][0]), "+f"(acc[mt][nt][1]),
                          "+f"(acc[mt][nt][2]), "+f"(acc[mt][nt][3])
                        : "r"(a[mt][0]), "r"(a[mt][1]), "r"(a[mt][2]), "r"(a[mt][3]),
                          "r"(b[nt][0]), "r"(b[nt][1]));
                }
        }
        __syncthreads();
    }

    if (cmode == 2 && bn >= 256) {
        // stop branch: sum over this CTA's 128 cols of relu(v)*w2[col]
        float myp[2][2];
        myp[0][0] = myp[0][1] = myp[1][0] = myp[1][1] = 0.f;
#pragma unroll
        for (int nt = 0; nt < 8; nt++)
#pragma unroll
            for (int e = 0; e < 4; e++) {
                int col = bn + wn + nt * 8 + tig * 2 + (e & 1);
                float wv = __ldg(w2 + (col - 256));
                float bv = __ldg(bias0 + col);
#pragma unroll
                for (int mt = 0; mt < 2; mt++) {
                    float v = fmaxf(acc[mt][nt][e] + bv, 0.f);
                    myp[mt][e >> 1] += v * wv;
                }
            }
        // reduce over tig group (lanes xor 1, xor 2)
#pragma unroll
        for (int mt = 0; mt < 2; mt++)
#pragma unroll
            for (int h = 0; h < 2; h++) {
                float v = myp[mt][h];
                v += __shfl_xor_sync(0xffffffffu, v, 1);
                v += __shfl_xor_sync(0xffffffffu, v, 2);
                myp[mt][h] = v;
            }
        if (tig == 0) {
            int wi = wn ? 1 : 0;
#pragma unroll
            for (int mt = 0; mt < 2; mt++)
#pragma unroll
                for (int h = 0; h < 2; h++)
                    spart[wi][wm + mt * 16 + grp + 8 * h] = myp[mt][h];
        }
        __syncthreads();
        if (tid < BM)
            stopP[(size_t)((bn - 256) >> 7) * M_DEC + bm + tid] =
                spart[0][tid] + spart[1][tid];
        return;
    }

    // standard / Hid epilogue
#pragma unroll
    for (int nt = 0; nt < 8; nt++) {
#pragma unroll
        for (int e = 0; e < 4; e++) {
            int col = bn + wn + nt * 8 + tig * 2 + (e & 1);
            if (col >= N) continue;
            float bv = 0.f;
            if (bias0) bv += __ldg(bias0 + col);
            if (bias1) bv += __ldg(bias1 + col);
#pragma unroll
            for (int mt = 0; mt < 2; mt++) {
                int row = bm + wm + mt * 16 + grp + ((e >> 1) << 3);
                float v = acc[mt][nt][e] + bv;
                if (dorelu) v = fmaxf(v, 0.f);
                if (doround) v = to_tf32(v);
                if (cmode == 0)
                    C[(size_t)row * N + col] = v;
                else if (cmode == 1)
                    C[(size_t)(row >> 6) * (64 * (size_t)N) + (size_t)col * 64 + (row & 63)] = v;
                else // cmode 2, Hid half: ldc = 256
                    C[(size_t)row * 256 + col] = v;
            }
        }
    }
}

// ---------------- stop finalize ----------------
__global__ void stopfin_k(const float* __restrict__ b2, float* __restrict__ out) {
    int r = blockIdx.x * 256 + threadIdx.x;
    if (r < M_DEC) out[r] = g_StopP[r] + g_StopP[M_DEC + r] + b2[0];
}

// ---------------- persistent recurrent LSTM (f32x2 packed FFMA) ----------------
__device__ __forceinline__ float sigmoidf_(float x) { return 1.f / (1.f + __expf(-x)); }

#define SEQ_NB 128
#define SEQ_NT 128

__global__ void __launch_bounds__(SEQ_NT, 1) lstm_seq(
    const float* __restrict__ encWhh, const float* __restrict__ decWhh,
    const int* __restrict__ tlen)
{
    __shared__ __align__(16) float2 Wse2[8][256];
    __shared__ __align__(16) float2 Wsd2[8][256];
    __shared__ __align__(16) float part[4][8][64];

    const int tid = threadIdx.x;
    const int blk = blockIdx.x;
    const int j0 = blk * 2;

    for (int idx = tid; idx < 8 * 256; idx += SEQ_NT) {
        int gl = idx >> 8, k = idx & 255;
        int g = gl >> 1, l = gl & 1;
        int row = g * 256 + j0 + l;
        float we = encWhh[row * 256 + k];
        float wd = decWhh[row * 256 + k];
        Wse2[gl][k] = make_float2(we, we);
        Wsd2[gl][k] = make_float2(wd, wd);
    }
    const int warp = tid >> 5, lane = tid & 31;
    const int b0  = (lane & 15) * 4;
    const int gl0 = (lane >> 4) * 4;
    const int kbeg = warp * 64;
    const int ub = tid & 63, ul = tid >> 6;
    const int uj = j0 + ul;
    float c_reg = 0.f;
    const int mylen = tlen[ub];
    __syncthreads();

    for (int s = 0; s < LT + MAXDEC; s++) {
        if (tid == 0) {
            unsigned int tgt = (unsigned int)(SEQ_NB * s);
            while (*(volatile unsigned int*)&g_bar < tgt) { }
        }
        __syncthreads();

        const int cur = s & 1, nxt = cur ^ 1;
        const bool enc = (s < LT);
        const float* hb = g_hbuf + cur * (D_H * NB_);
        const float2 (*Ws)[256] = enc ? Wse2 : Wsd2;

        // prefetch x-part gate values (independent of h)
        const float* XG = enc ? (g_XencG + (size_t)s * (G4 * NB_))
                              : (g_XdG  + (size_t)(s - LT) * ((size_t)G4 * NB_));
        float gvx[4];
#pragma unroll
        for (int g = 0; g < 4; g++)
            gvx[g] = __ldcg(XG + ((g * 256 + uj) << 6) + ub);

        unsigned long long accp[2][4];
#pragma unroll
        for (int p = 0; p < 2; p++)
#pragma unroll
            for (int g = 0; g < 4; g++) accp[p][g] = 0ull;

#pragma unroll 8
        for (int k = kbeg; k < kbeg + 64; k++) {
            ulonglong2 hq = __ldcg((const ulonglong2*)(hb + k * 64 + b0));
            unsigned long long w0 = *(const unsigned long long*)&Ws[gl0 + 0][k];
            unsigned long long w1 = *(const unsigned long long*)&Ws[gl0 + 1][k];
            unsigned long long w2 = *(const unsigned long long*)&Ws[gl0 + 2][k];
            unsigned long long w3 = *(const unsigned long long*)&Ws[gl0 + 3][k];
            asm("fma.rn.f32x2 %0, %1, %2, %0;" : "+l"(accp[0][0]) : "l"(hq.x), "l"(w0));
            asm("fma.rn.f32x2 %0, %1, %2, %0;" : "+l"(accp[1][0]) : "l"(hq.y), "l"(w0));
            asm("fma.rn.f32x2 %0, %1, %2, %0;" : "+l"(accp[0][1]) : "l"(hq.x), "l"(w1));
            asm("fma.rn.f32x2 %0, %1, %2, %0;" : "+l"(accp[1][1]) : "l"(hq.y), "l"(w1));
            asm("fma.rn.f32x2 %0, %1, %2, %0;" : "+l"(accp[0][2]) : "l"(hq.x), "l"(w2));
            asm("fma.rn.f32x2 %0, %1, %2, %0;" : "+l"(accp[1][2]) : "l"(hq.y), "l"(w2));
            asm("fma.rn.f32x2 %0, %1, %2, %0;" : "+l"(accp[0][3]) : "l"(hq.x), "l"(w3));
            asm("fma.rn.f32x2 %0, %1, %2, %0;" : "+l"(accp[1][3]) : "l"(hq.y), "l"(w3));
        }
#pragma unroll
        for (int g = 0; g < 4; g++) {
            float2 f0 = *(float2*)&accp[0][g];
            float2 f1 = *(float2*)&accp[1][g];
            *(float4*)&part[warp][gl0 + g][b0] = make_float4(f0.x, f0.y, f1.x, f1.y);
        }
        __syncthreads();

        float gv[4];
#pragma unroll
        for (int g = 0; g < 4; g++) {
            int gl = g * 2 + ul;
            gv[g] = part[0][gl][ub] + part[1][gl][ub] + part[2][gl][ub] + part[3][gl][ub]
                  + gvx[g];
        }
        if (s == LT)
            c_reg = __ldcg(hb + uj * 64 + ub);

        float iv = sigmoidf_(gv[0]);
        float fv = sigmoidf_(gv[1]);
        float gg = tanhf(gv[2]);
        float ov = sigmoidf_(gv[3]);
        float c2 = fv * c_reg + iv * gg;
        float h2 = ov * tanhf(c2);
        float hnew;
        if (enc) {
            bool m = (s < mylen);
            float hold = __ldcg(hb + uj * 64 + ub);
            c_reg = m ? c2 : c_reg;
            hnew  = m ? h2 : hold;
        } else {
            c_reg = c2;
            hnew  = h2;
            g_H[(size_t)(s - LT) * (NB_ * D_H) + ub * D_H + uj] = to_tf32(h2);
        }
        g_hbuf[nxt * (D_H * NB_) + uj * 64 + ub] = hnew;

        __threadfence();
        __syncthreads();
        if (tid == 0) atomicAdd(&g_bar, 1u);
    }
}

// ---------------- launch ----------------
extern "C" void kernel_launch(void* const* d_in, const int* in_sizes, int n_in,
                              void* d_out, int out_size) {
    const int*   token_pad     = (const int*)  d_in[0];
    const int*   token_lengths = (const int*)  d_in[1];
    const float* S_true        = (const float*)d_in[2];
    const float* emb           = (const float*)d_in[3];
    const float* enc_Wih       = (const float*)d_in[4];
    const float* enc_Whh       = (const float*)d_in[5];
    const float* enc_bih       = (const float*)d_in[6];
    const float* enc_bhh       = (const float*)d_in[7];
    const float* dec_Wih       = (const float*)d_in[8];
    const float* dec_Whh       = (const float*)d_in[9];
    const float* dec_bih       = (const float*)d_in[10];
    const float* dec_bhh       = (const float*)d_in[11];
    const float* pre_W         = (const float*)d_in[12];
    const float* pre_b         = (const float*)d_in[13];
    const float* post_W1       = (const float*)d_in[14];
    const float* post_b1       = (const float*)d_in[15];
    const float* post_W2       = (const float*)d_in[16];
    const float* post_b2       = (const float*)d_in[17];
    const float* stop_W1       = (const float*)d_in[18];
    const float* stop_b1       = (const float*)d_in[19];
    const float* stop_W2       = (const float*)d_in[20];
    const float* stop_b2       = (const float*)d_in[21];
    float* out = (float*)d_out;

    float *pTE, *pXencG, *pXd, *pXdG, *pH, *pHid, *pWr, *pStopP, *pBcat;
    cudaGetSymbolAddress((void**)&pTE,    g_TE);
    cudaGetSymbolAddress((void**)&pXencG, g_XencG);
    cudaGetSymbolAddress((void**)&pXd,    g_Xd);
    cudaGetSymbolAddress((void**)&pXdG,   g_XdG);
    cudaGetSymbolAddress((void**)&pH,     g_H);
    cudaGetSymbolAddress((void**)&pHid,   g_Hid);
    cudaGetSymbolAddress((void**)&pWr,    g_Wr);
    cudaGetSymbolAddress((void**)&pStopP, g_StopP);
    cudaGetSymbolAddress((void**)&pBcat,  g_bcat);

    init_k<<<128, 256>>>();
    biascat_k<<<2, 256>>>(post_b1, stop_b1);

    // round weights into scratch
    round_pad<<<(1024*256+255)/256, 256>>>(enc_Wih, pWr + W_ENC,   1024, 1024, 256, 256);
    round_pad<<<(1024*256+255)/256, 256>>>(dec_Wih, pWr + W_DEC,   1024, 1024, 256, 256);
    round_pad<<<(256*KP_S+255)/256, 256>>>(pre_W,   pWr + W_PRE,   256,  256,  D_S, KP_S);
    round_pad<<<(256*256+255)/256,  256>>>(post_W1, pWr + W_P1S,            256, 256, 256, 256);
    round_pad<<<(256*256+255)/256,  256>>>(stop_W1, pWr + W_P1S + 256*256,  256, 256, 256, 256);
    round_pad<<<(640*256+255)/256,  256>>>(post_W2, pWr + W_POST2, D_S,  640, 256, 256);

    gather_emb<<<M_ENC, 256>>>(token_pad, emb, pTE);

    // enc gate x-part
    gemm_tc<0><<<dim3(M_ENC/128, G4/128), 256>>>(pTE, 256, 0, M_ENC, 256,
        pWr + W_ENC, 256, enc_bih, enc_bhh, pXencG, M_ENC, G4, 256, 1, 0, 0, nullptr, nullptr);
    // pre-net straight from S_true (mask + in-register rounding)
    gemm_tc<1><<<dim3(M_DEC/128, D_H/128), 256>>>(S_true, D_S, 64, 51200, D_S,
        pWr + W_PRE, KP_S, pre_b, nullptr, pXd, M_DEC, D_H, KP_S, 0, 0, 1, nullptr, nullptr);
    // dec gate x-part
    gemm_tc<0><<<dim3(M_DEC/128, G4/128), 256>>>(pXd, 256, 0, M_DEC, 256,
        pWr + W_DEC, 256, dec_bih, dec_bhh, pXdG, M_DEC, G4, 256, 1, 0, 0, nullptr, nullptr);
    // sequential LSTM
    lstm_seq<<<SEQ_NB, SEQ_NT>>>(enc_Whh, dec_Whh, token_lengths);
    // fused post1 + stop1 + stop2-reduce  (N = 512)
    gemm_tc<0><<<dim3(M_DEC/128, 4), 256>>>(pH, 256, 0, M_DEC, 256,
        pWr + W_P1S, 256, pBcat, nullptr, pHid, M_DEC, 512, 256, 2, 1, 1, stop_W2, pStopP);
    // post2 -> S_pred
    gemm_tc<0><<<dim3(M_DEC/128, (D_S+127)/128), 256>>>(pHid, 256, 0, M_DEC, 256,
        pWr + W_POST2, 256, post_b2, nullptr, out, M_DEC, D_S, 256, 0, 0, 0, nullptr, nullptr);
    // stop finalize
    stopfin_k<<<(M_DEC+255)/256, 256>>>(stop_b2, out + STOP_OFF);
}

// round 5
// speedup vs baseline: 1.7105x; 1.1934x over previous
#include <cuda_runtime.h>
#include <cuda_bf16.h>
#include <math.h>
#include <stdint.h>

// ---------------- problem constants ----------------
#define D_H 256
#define D_S 552
#define LT  128
#define NB_ 64
#define MAXDEC 1000
#define G4 1024
#define M_ENC (LT*NB_)       // 8192
#define M_DEC (MAXDEC*NB_)   // 64000
#define STOP_OFF ((size_t)M_DEC * D_S)
#define KP_S 560

// ---------------- device scratch ----------------
__device__ __align__(256) float g_TE[M_ENC * D_H];
__device__ __align__(256) float g_XencG[M_ENC * G4];
__device__ __align__(256) float g_Xd[(size_t)M_DEC * D_H];
__device__ __align__(256) float g_XdG[(size_t)M_DEC * G4];
__device__ __align__(256) float g_H[(size_t)M_DEC * D_H];
__device__ __align__(256) float g_Hid[(size_t)M_DEC * D_H];
__device__ __align__(256) float g_StopP[M_DEC];
__device__ __align__(256) float g_Wr[995328];
__device__ __align__(256) float g_bcat[512];
__device__ float g_hbuf[2 * D_H * NB_];
__device__ unsigned int g_bar;

// weight scratch offsets (floats)
#define W_ENC   0
#define W_DEC   262144
#define W_PRE   524288      // [256][560]
#define W_P1S   667648      // [512][256]
#define W_POST2 798720      // [768][256] (rows >=552 zero)

__device__ __forceinline__ float to_tf32(float x) {
    float r; asm("cvt.rna.tf32.f32 %0, %1;" : "=f"(r) : "f"(x)); return r;
}

// ---------------- init ----------------
__global__ void init_k() {
    int i = blockIdx.x * blockDim.x + threadIdx.x;
    if (i == 0) g_bar = 0u;
    if (i < 2 * D_H * NB_) g_hbuf[i] = 0.f;
}

__global__ void biascat_k(const float* __restrict__ b1, const float* __restrict__ b2) {
    int i = threadIdx.x + blockIdx.x * 256;
    if (i < 512) g_bcat[i] = (i < 256) ? b1[i] : b2[i - 256];
}

__global__ void round_pad(const float* __restrict__ src, float* __restrict__ dst,
                          int Rsrc, int Rdst, int C, int Cp) {
    int idx = blockIdx.x * 256 + threadIdx.x;
    if (idx >= Rdst * Cp) return;
    int r = idx / Cp, c = idx - r * Cp;
    float v = (r < Rsrc && c < C) ? to_tf32(src[(size_t)r * C + c]) : 0.f;
    dst[idx] = v;
}

__global__ void gather_emb(const int* __restrict__ tok, const float* __restrict__ emb,
                           float* __restrict__ te) {
    int r = blockIdx.x;
    int k = threadIdx.x;
    te[r * D_H + k] = to_tf32(emb[tok[r] * D_H + k]);
}

// ---------------- tf32 tensor-core GEMM (128x256 tile, 64x64 warp tile, 3-stage) ----------------
#define BM 128
#define BN 256
#define BK 16
#define SL 20
#define ST_AGES 3
#define AOFF(s) ((s) * (BM * SL))
#define BOFF(s) (ST_AGES * BM * SL + (s) * (BN * SL))
#define GEMM_SMEM (ST_AGES * (BM + BN) * SL * 4)

__device__ __forceinline__ void cp16(uint32_t s, const void* g) {
    asm volatile("cp.async.cg.shared.global [%0], [%1], 16;" :: "r"(s), "l"(g));
}

template<int RA>
__global__ void __launch_bounds__(256, 1) gemm_tc(
    const float* __restrict__ A, int lda, int rowlo, int rowhi, int kvalid,
    const float* __restrict__ B, int ldb,
    const float* __restrict__ bias0, const float* __restrict__ bias1,
    float* __restrict__ C, int M, int N, int K,
    int cmode, int dorelu, int doround,
    const float* __restrict__ w2, float* __restrict__ stopP)
{
    extern __shared__ float smp[];
    __shared__ float spart[4][BM];

    const int tid  = threadIdx.x;
    const int bm   = blockIdx.x * BM;
    const int bn   = blockIdx.y * BN;
    const int warp = tid >> 5, lane = tid & 31;
    const int wm   = (warp & 1) * 64;
    const int wn   = (warp >> 1) * 64;
    const int grp  = lane >> 2;
    const int tig  = lane & 3;

    float acc[4][8][4];
#pragma unroll
    for (int i = 0; i < 4; i++)
#pragma unroll
        for (int j = 0; j < 8; j++)
#pragma unroll
            for (int e = 0; e < 4; e++) acc[i][j][e] = 0.f;

    const int T = K / BK;

#define LOAD_TILE(t)                                                            \
    {                                                                           \
        int k0 = (t) * BK;                                                      \
        int sb = (t) % ST_AGES;                                                 \
        _Pragma("unroll")                                                       \
        for (int i = 0; i < 2; i++) {                                           \
            int f = i * 256 + tid, row = f >> 2, seg = (f & 3) * 4;             \
            int ar = bm + row, kk = k0 + seg;                                   \
            float* da = smp + AOFF(sb) + row * SL + seg;                        \
            if (ar >= rowlo && ar < rowhi && kk < kvalid)                       \
                cp16((uint32_t)__cvta_generic_to_shared(da),                    \
                     A + (size_t)ar * lda + kk);                                \
            else                                                                \
                *(float4*)da = make_float4(0.f, 0.f, 0.f, 0.f);                 \
        }                                                                       \
        _Pragma("unroll")                                                       \
        for (int i = 0; i < 4; i++) {                                           \
            int f = i * 256 + tid, row = f >> 2, seg = (f & 3) * 4;             \
            float* db = smp + BOFF(sb) + row * SL + seg;                        \
            cp16((uint32_t)__cvta_generic_to_shared(db),                        \
                 B + (size_t)(bn + row) * ldb + k0 + seg);                      \
        }                                                                       \
        asm volatile("cp.async.commit_group;" ::: "memory");                    \
    }

    LOAD_TILE(0);
    LOAD_TILE(1);

    for (int t = 0; t < T; t++) {
        asm volatile("cp.async.wait_group 1;" ::: "memory");
        __syncthreads();
        if (t + 2 < T) LOAD_TILE(t + 2);

        const uint32_t* as = reinterpret_cast<const uint32_t*>(smp + AOFF(t % ST_AGES));
        const uint32_t* bs = reinterpret_cast<const uint32_t*>(smp + BOFF(t % ST_AGES));

#pragma unroll
        for (int kk = 0; kk < BK; kk += 8) {
            uint32_t a[4][4], b[8][2];
            const int c0 = kk + tig;
#pragma unroll
            for (int mt = 0; mt < 4; mt++) {
                int r0 = wm + mt * 16 + grp;
                a[mt][0] = as[r0 * SL + c0];
                a[mt][1] = as[(r0 + 8) * SL + c0];
                a[mt][2] = as[r0 * SL + c0 + 4];
                a[mt][3] = as[(r0 + 8) * SL + c0 + 4];
                if (RA) {
#pragma unroll
                    for (int q = 0; q < 4; q++)
                        a[mt][q] = __float_as_uint(to_tf32(__uint_as_float(a[mt][q])));
                }
            }
#pragma unroll
            for (int nt = 0; nt < 8; nt++) {
                int n0 = wn + nt * 8 + grp;
                b[nt][0] = bs[n0 * SL + c0];
                b[nt][1] = bs[n0 * SL + c0 + 4];
            }
#pragma unroll
            for (int mt = 0; mt < 4; mt++)
#pragma unroll
                for (int nt = 0; nt < 8; nt++) {
                    asm volatile(
                        "mma.sync.aligned.m16n8k8.row.col.f32.tf32.tf32.f32 "
                        "{%0,%1,%2,%3}, {%4,%5,%6,%7}, {%8,%9}, {%0,%1,%2,%3};"
                        : "+f"(acc[mt][nt][0]), "+f"(acc[mt][nt][1]),
                          "+f"(acc[mt][nt][2]), "+f"(acc[mt][nt][3])
                        : "r"(a[mt][0]), "r"(a[mt][1]), "r"(a[mt][2]), "r"(a[mt][3]),
                          "r"(b[nt][0]), "r"(b[nt][1]));
                }
        }
        __syncthreads();
    }
#undef LOAD_TILE

    if (cmode == 2 && bn == 256) {
        // stop branch: all 256 stop cols in this tile; reduce relu(v)*w2 per row
        float myp[4][2];
#pragma unroll
        for (int mt = 0; mt < 4; mt++) { myp[mt][0] = 0.f; myp[mt][1] = 0.f; }
#pragma unroll
        for (int nt = 0; nt < 8; nt++)
#pragma unroll
            for (int e = 0; e < 4; e++) {
                int col = bn + wn + nt * 8 + tig * 2 + (e & 1);
                float wv = __ldg(w2 + (col - 256));
                float bv = __ldg(bias0 + col);
#pragma unroll
                for (int mt = 0; mt < 4; mt++) {
                    float v = fmaxf(acc[mt][nt][e] + bv, 0.f);
                    myp[mt][e >> 1] += v * wv;
                }
            }
#pragma unroll
        for (int mt = 0; mt < 4; mt++)
#pragma unroll
            for (int h = 0; h < 2; h++) {
                float v = myp[mt][h];
                v += __shfl_xor_sync(0xffffffffu, v, 1);
                v += __shfl_xor_sync(0xffffffffu, v, 2);
                myp[mt][h] = v;
            }
        if (tig == 0) {
            int wi = warp >> 1;
#pragma unroll
            for (int mt = 0; mt < 4; mt++)
#pragma unroll
                for (int h = 0; h < 2; h++)
                    spart[wi][wm + mt * 16 + grp + 8 * h] = myp[mt][h];
        }
        __syncthreads();
        if (tid < BM)
            stopP[bm + tid] = spart[0][tid] + spart[1][tid] + spart[2][tid] + spart[3][tid];
        return;
    }

    // standard / Hid epilogue
#pragma unroll
    for (int nt = 0; nt < 8; nt++) {
#pragma unroll
        for (int e = 0; e < 4; e++) {
            int col = bn + wn + nt * 8 + tig * 2 + (e & 1);
            if (col >= N) continue;
            float bv = 0.f;
            if (bias0) bv += __ldg(bias0 + col);
            if (bias1) bv += __ldg(bias1 + col);
#pragma unroll
            for (int mt = 0; mt < 4; mt++) {
                int row = bm + wm + mt * 16 + grp + ((e >> 1) << 3);
                float v = acc[mt][nt][e] + bv;
                if (dorelu) v = fmaxf(v, 0.f);
                if (doround) v = to_tf32(v);
                if (cmode == 0)
                    C[(size_t)row * N + col] = v;
                else if (cmode == 1)
                    C[(size_t)(row >> 6) * (64 * (size_t)N) + (size_t)col * 64 + (row & 63)] = v;
                else
                    C[(size_t)row * 256 + col] = v;
            }
        }
    }
}

// ---------------- stop finalize ----------------
__global__ void stopfin_k(const float* __restrict__ b2, float* __restrict__ out) {
    int r = blockIdx.x * 256 + threadIdx.x;
    if (r < M_DEC) out[r] = g_StopP[r] + b2[0];
}

// ---------------- persistent recurrent LSTM: 256 threads, 8-warp K split ----------------
__device__ __forceinline__ float sigmoidf_(float x) { return 1.f / (1.f + __expf(-x)); }

#define SEQ_NB 128
#define SEQ_NT 256

__global__ void __launch_bounds__(SEQ_NT, 1) lstm_seq(
    const float* __restrict__ encWhh, const float* __restrict__ decWhh,
    const int* __restrict__ tlen)
{
    __shared__ __align__(16) float  Wse[8][257];    // enc weights, scalar
    __shared__ __align__(16) float2 Wsd2[8][256];   // dec weights, duplicated pair
    __shared__ __align__(16) float  part[8][8][64];

    const int tid = threadIdx.x;
    const int blk = blockIdx.x;
    const int j0 = blk * 2;

    for (int idx = tid; idx < 8 * 256; idx += SEQ_NT) {
        int gl = idx >> 8, k = idx & 255;
        int g = gl >> 1, l = gl & 1;
        int row = g * 256 + j0 + l;
        Wse[gl][k] = encWhh[row * 256 + k];
        float wd = decWhh[row * 256 + k];
        Wsd2[gl][k] = make_float2(wd, wd);
    }
    const int warp = tid >> 5, lane = tid & 31;
    const int b0  = (lane & 15) * 4;
    const int gl0 = (lane >> 4) * 4;
    const int kbeg = warp * 32;
    const int ub = tid & 63, ul = tid >> 6;
    const int uj = j0 + ul;
    const bool upd = (tid < 128);
    float c_reg = 0.f;
    const int mylen = upd ? tlen[ub] : 0;
    __syncthreads();

    for (int s = 0; s < LT + MAXDEC; s++) {
        if (tid == 0) {
            unsigned int tgt = (unsigned int)(SEQ_NB * s);
            while (*(volatile unsigned int*)&g_bar < tgt) { }
        }
        __syncthreads();

        const int cur = s & 1, nxt = cur ^ 1;
        const bool enc = (s < LT);
        const float* hb = g_hbuf + cur * (D_H * NB_);

        // prefetch x-part gate values
        const float* XG = enc ? (g_XencG + (size_t)s * (G4 * NB_))
                              : (g_XdG  + (size_t)(s - LT) * ((size_t)G4 * NB_));
        float gvx[4];
        if (upd) {
#pragma unroll
            for (int g = 0; g < 4; g++)
                gvx[g] = __ldcg(XG + ((g * 256 + uj) << 6) + ub);
        }

        if (enc) {
            float acc[4][4];
#pragma unroll
            for (int i = 0; i < 4; i++)
#pragma unroll
                for (int g = 0; g < 4; g++) acc[i][g] = 0.f;
#pragma unroll 8
            for (int k = kbeg; k < kbeg + 32; k++) {
                float4 h4 = __ldcg((const float4*)(hb + k * 64 + b0));
                float w0 = Wse[gl0 + 0][k], w1 = Wse[gl0 + 1][k];
                float w2 = Wse[gl0 + 2][k], w3 = Wse[gl0 + 3][k];
                acc[0][0] += h4.x * w0; acc[1][0] += h4.y * w0; acc[2][0] += h4.z * w0; acc[3][0] += h4.w * w0;
                acc[0][1] += h4.x * w1; acc[1][1] += h4.y * w1; acc[2][1] += h4.z * w1; acc[3][1] += h4.w * w1;
                acc[0][2] += h4.x * w2; acc[1][2] += h4.y * w2; acc[2][2] += h4.z * w2; acc[3][2] += h4.w * w2;
                acc[0][3] += h4.x * w3; acc[1][3] += h4.y * w3; acc[2][3] += h4.z * w3; acc[3][3] += h4.w * w3;
            }
#pragma unroll
            for (int g = 0; g < 4; g++)
                *(float4*)&part[warp][gl0 + g][b0] =
                    make_float4(acc[0][g], acc[1][g], acc[2][g], acc[3][g]);
        } else {
            unsigned long long accp[2][4];
#pragma unroll
            for (int p = 0; p < 2; p++)
#pragma unroll
                for (int g = 0; g < 4; g++) accp[p][g] = 0ull;
#pragma unroll 8
            for (int k = kbeg; k < kbeg + 32; k++) {
                ulonglong2 hq = __ldcg((const ulonglong2*)(hb + k * 64 + b0));
                unsigned long long w0 = *(const unsigned long long*)&Wsd2[gl0 + 0][k];
                unsigned long long w1 = *(const unsigned long long*)&Wsd2[gl0 + 1][k];
                unsigned long long w2 = *(const unsigned long long*)&Wsd2[gl0 + 2][k];
                unsigned long long w3 = *(const unsigned long long*)&Wsd2[gl0 + 3][k];
                asm("fma.rn.f32x2 %0, %1, %2, %0;" : "+l"(accp[0][0]) : "l"(hq.x), "l"(w0));
                asm("fma.rn.f32x2 %0, %1, %2, %0;" : "+l"(accp[1][0]) : "l"(hq.y), "l"(w0));
                asm("fma.rn.f32x2 %0, %1, %2, %0;" : "+l"(accp[0][1]) : "l"(hq.x), "l"(w1));
                asm("fma.rn.f32x2 %0, %1, %2, %0;" : "+l"(accp[1][1]) : "l"(hq.y), "l"(w1));
                asm("fma.rn.f32x2 %0, %1, %2, %0;" : "+l"(accp[0][2]) : "l"(hq.x), "l"(w2));
                asm("fma.rn.f32x2 %0, %1, %2, %0;" : "+l"(accp[1][2]) : "l"(hq.y), "l"(w2));
                asm("fma.rn.f32x2 %0, %1, %2, %0;" : "+l"(accp[0][3]) : "l"(hq.x), "l"(w3));
                asm("fma.rn.f32x2 %0, %1, %2, %0;" : "+l"(accp[1][3]) : "l"(hq.y), "l"(w3));
            }
#pragma unroll
            for (int g = 0; g < 4; g++) {
                float2 f0 = *(float2*)&accp[0][g];
                float2 f1 = *(float2*)&accp[1][g];
                *(float4*)&part[warp][gl0 + g][b0] = make_float4(f0.x, f0.y, f1.x, f1.y);
            }
        }
        __syncthreads();

        if (upd) {
            float gv[4];
#pragma unroll
            for (int g = 0; g < 4; g++) {
                int gl = g * 2 + ul;
                float v = gvx[g];
#pragma unroll
                for (int w = 0; w < 8; w++) v += part[w][gl][ub];
                gv[g] = v;
            }
            if (s == LT)
                c_reg = __ldcg(hb + uj * 64 + ub);

            float iv = sigmoidf_(gv[0]);
            float fv = sigmoidf_(gv[1]);
            float gg = tanhf(gv[2]);
            float ov = sigmoidf_(gv[3]);
            float c2 = fv * c_reg + iv * gg;
            float h2 = ov * tanhf(c2);
            float hnew;
            if (enc) {
                bool m = (s < mylen);
                float hold = __ldcg(hb + uj * 64 + ub);
                c_reg = m ? c2 : c_reg;
                hnew  = m ? h2 : hold;
            } else {
                c_reg = c2;
                hnew  = h2;
                g_H[(size_t)(s - LT) * (NB_ * D_H) + ub * D_H + uj] = to_tf32(h2);
            }
            g_hbuf[nxt * (D_H * NB_) + uj * 64 + ub] = hnew;
        }

        __threadfence();
        __syncthreads();
        if (tid == 0) atomicAdd(&g_bar, 1u);
    }
}

// ---------------- launch ----------------
extern "C" void kernel_launch(void* const* d_in, const int* in_sizes, int n_in,
                              void* d_out, int out_size) {
    const int*   token_pad     = (const int*)  d_in[0];
    const int*   token_lengths = (const int*)  d_in[1];
    const float* S_true        = (const float*)d_in[2];
    const float* emb           = (const float*)d_in[3];
    const float* enc_Wih       = (const float*)d_in[4];
    const float* enc_Whh       = (const float*)d_in[5];
    const float* enc_bih       = (const float*)d_in[6];
    const float* enc_bhh       = (const float*)d_in[7];
    const float* dec_Wih       = (const float*)d_in[8];
    const float* dec_Whh       = (const float*)d_in[9];
    const float* dec_bih       = (const float*)d_in[10];
    const float* dec_bhh       = (const float*)d_in[11];
    const float* pre_W         = (const float*)d_in[12];
    const float* pre_b         = (const float*)d_in[13];
    const float* post_W1       = (const float*)d_in[14];
    const float* post_b1       = (const float*)d_in[15];
    const float* post_W2       = (const float*)d_in[16];
    const float* post_b2       = (const float*)d_in[17];
    const float* stop_W1       = (const float*)d_in[18];
    const float* stop_b1       = (const float*)d_in[19];
    const float* stop_W2       = (const float*)d_in[20];
    const float* stop_b2       = (const float*)d_in[21];
    float* out = (float*)d_out;

    float *pTE, *pXencG, *pXd, *pXdG, *pH, *pHid, *pWr, *pStopP, *pBcat;
    cudaGetSymbolAddress((void**)&pTE,    g_TE);
    cudaGetSymbolAddress((void**)&pXencG, g_XencG);
    cudaGetSymbolAddress((void**)&pXd,    g_Xd);
    cudaGetSymbolAddress((void**)&pXdG,   g_XdG);
    cudaGetSymbolAddress((void**)&pH,     g_H);
    cudaGetSymbolAddress((void**)&pHid,   g_Hid);
    cudaGetSymbolAddress((void**)&pWr,    g_Wr);
    cudaGetSymbolAddress((void**)&pStopP, g_StopP);
    cudaGetSymbolAddress((void**)&pBcat,  g_bcat);

    cudaFuncSetAttribute(gemm_tc<0>, cudaFuncAttributeMaxDynamicSharedMemorySize, GEMM_SMEM);
    cudaFuncSetAttribute(gemm_tc<1>, cudaFuncAttributeMaxDynamicSharedMemorySize, GEMM_SMEM);

    init_k<<<128, 256>>>();
    biascat_k<<<2, 256>>>(post_b1, stop_b1);

    round_pad<<<(1024*256+255)/256, 256>>>(enc_Wih, pWr + W_ENC,   1024, 1024, 256, 256);
    round_pad<<<(1024*256+255)/256, 256>>>(dec_Wih, pWr + W_DEC,   1024, 1024, 256, 256);
    round_pad<<<(256*KP_S+255)/256, 256>>>(pre_W,   pWr + W_PRE,   256,  256,  D_S, KP_S);
    round_pad<<<(256*256+255)/256,  256>>>(post_W1, pWr + W_P1S,            256, 256, 256, 256);
    round_pad<<<(256*256+255)/256,  256>>>(stop_W1, pWr + W_P1S + 256*256,  256, 256, 256, 256);
    round_pad<<<(768*256+255)/256,  256>>>(post_W2, pWr + W_POST2, D_S,  768, 256, 256);

    gather_emb<<<M_ENC, 256>>>(token_pad, emb, pTE);

    // enc gate x-part -> [t][gcol][b]
    gemm_tc<0><<<dim3(M_ENC/128, G4/256), 256, GEMM_SMEM>>>(pTE, 256, 0, M_ENC, 256,
        pWr + W_ENC, 256, enc_bih, enc_bhh, pXencG, M_ENC, G4, 256, 1, 0, 0, nullptr, nullptr);
    // pre-net straight from S_true (mask + in-register rounding)
    gemm_tc<1><<<dim3(M_DEC/128, 1), 256, GEMM_SMEM>>>(S_true, D_S, 64, 51200, D_S,
        pWr + W_PRE, KP_S, pre_b, nullptr, pXd, M_DEC, D_H, KP_S, 0, 0, 1, nullptr, nullptr);
    // dec gate x-part -> [t][gcol][b]
    gemm_tc<0><<<dim3(M_DEC/128, G4/256), 256, GEMM_SMEM>>>(pXd, 256, 0, M_DEC, 256,
        pWr + W_DEC, 256, dec_bih, dec_bhh, pXdG, M_DEC, G4, 256, 1, 0, 0, nullptr, nullptr);
    // sequential LSTM
    lstm_seq<<<SEQ_NB, SEQ_NT>>>(enc_Whh, dec_Whh, token_lengths);
    // fused post1 + stop1 + stop2-reduce (N=512: tile0 -> Hid, tile1 -> stop)
    gemm_tc<0><<<dim3(M_DEC/128, 2), 256, GEMM_SMEM>>>(pH, 256, 0, M_DEC, 256,
        pWr + W_P1S, 256, pBcat, nullptr, pHid, M_DEC, 512, 256, 2, 1, 1, stop_W2, pStopP);
    // post2 -> S_pred
    gemm_tc<0><<<dim3(M_DEC/128, 3), 256, GEMM_SMEM>>>(pHid, 256, 0, M_DEC, 256,
        pWr + W_POST2, 256, post_b2, nullptr, out, M_DEC, D_S, 256, 0, 0, 0, nullptr, nullptr);
    // stop finalize
    stopfin_k<<<(M_DEC+255)/256, 256>>>(stop_b2, out + STOP_OFF);
}

// round 7
// speedup vs baseline: 2.0142x; 1.1775x over previous
#include <cuda_runtime.h>
#include <cuda_bf16.h>
#include <math.h>
#include <stdint.h>

// ---------------- problem constants ----------------
#define D_H 256
#define D_S 552
#define LT  128
#define NB_ 64
#define MAXDEC 1000
#define G4 1024
#define M_ENC (LT*NB_)       // 8192
#define M_DEC (MAXDEC*NB_)   // 64000
#define M_VAL 51200          // rows with non-trivial S_in (t in [0,800)); rows 0..63 masked in-GEMM
#define STOP_OFF ((size_t)M_DEC * D_S)
#define KP_S 560
#define NSEG 4
#define SEG_STEPS 250
#define SEG_ROWS  (SEG_STEPS*NB_)   // 16000

// ---------------- device scratch ----------------
__device__ __align__(256) float g_TE[M_ENC * D_H];
__device__ __align__(256) float g_XencG[M_ENC * G4];
__device__ __align__(256) float g_Xd[(size_t)M_VAL * D_H];
__device__ __align__(256) float g_XdG[(size_t)M_VAL * G4];
__device__ __align__(256) float g_H[(size_t)M_DEC * D_H];
__device__ __align__(256) float g_Hid[(size_t)M_DEC * D_H];
__device__ __align__(256) float g_StopP[M_DEC];
__device__ __align__(256) float g_Wr[995328];
__device__ __align__(256) float g_bcat[512];
__device__ __align__(256) float g_cvec[G4];
__device__ float g_hbuf[2 * D_H * NB_];
__device__ float g_cbuf[D_H * NB_];
__device__ unsigned int g_bar;

#define W_ENC   0
#define W_DEC   262144
#define W_PRE   524288      // [256][560]
#define W_P1S   667648      // [512][256]
#define W_POST2 798720      // [768][256]

__device__ __forceinline__ float to_tf32(float x) {
    float r; asm("cvt.rna.tf32.f32 %0, %1;" : "=f"(r) : "f"(x)); return r;
}

// ---------------- fused prep: init + bias concat + all weight rounding ----------------
#define P_HB  32768
#define P_BC  (P_HB + 512)
#define P_ENC (P_BC + 262144)
#define P_DEC (P_ENC + 262144)
#define P_PRE (P_DEC + 143360)
#define P_W1  (P_PRE + 65536)
#define P_S1  (P_W1 + 65536)
#define P_W2  (P_S1 + 196608)      // 1028608 total

__global__ void prep_k(const float* __restrict__ encWih, const float* __restrict__ decWih,
                       const float* __restrict__ preW,  const float* __restrict__ postW1,
                       const float* __restrict__ stopW1,const float* __restrict__ postW2,
                       const float* __restrict__ b1,    const float* __restrict__ b2) {
    int idx = blockIdx.x * 256 + threadIdx.x;
    if (idx == 0) g_bar = 0u;
    if (idx < P_HB) { g_hbuf[idx] = 0.f; return; }
    if (idx < P_BC) { int i = idx - P_HB; g_bcat[i] = (i < 256) ? b1[i] : b2[i - 256]; return; }
    if (idx < P_ENC){ int i = idx - P_BC; g_Wr[W_ENC + i] = to_tf32(encWih[i]); return; }
    if (idx < P_DEC){ int i = idx - P_ENC; g_Wr[W_DEC + i] = to_tf32(decWih[i]); return; }
    if (idx < P_PRE){ int i = idx - P_DEC; int r = i / KP_S, c = i - r * KP_S;
                      g_Wr[W_PRE + i] = (c < D_S) ? to_tf32(preW[r * D_S + c]) : 0.f; return; }
    if (idx < P_W1) { int i = idx - P_PRE; g_Wr[W_P1S + i] = to_tf32(postW1[i]); return; }
    if (idx < P_S1) { int i = idx - P_W1;  g_Wr[W_P1S + 65536 + i] = to_tf32(stopW1[i]); return; }
    if (idx < P_W2) { int i = idx - P_S1;  int r = i >> 8;
                      g_Wr[W_POST2 + i] = (r < D_S) ? to_tf32(postW2[i]) : 0.f; return; }
}

__global__ void gather_emb(const int* __restrict__ tok, const float* __restrict__ emb,
                           float* __restrict__ te) {
    int r = blockIdx.x;
    int k = threadIdx.x;
    te[r * D_H + k] = to_tf32(emb[tok[r] * D_H + k]);
}

// constant decoder gate x-part for t==0 / t>=800 (S_in row == 0)
__global__ void cvec_k(const float* __restrict__ pre_b,
                       const float* __restrict__ bih, const float* __restrict__ bhh) {
    int n = blockIdx.x * 8 + (threadIdx.x >> 5);
    int lane = threadIdx.x & 31;
    float acc = 0.f;
#pragma unroll
    for (int k = lane; k < 256; k += 32)
        acc += to_tf32(pre_b[k]) * g_Wr[W_DEC + n * 256 + k];
#pragma unroll
    for (int o = 16; o; o >>= 1) acc += __shfl_down_sync(0xffffffffu, acc, o);
    if (lane == 0) g_cvec[n] = acc + bih[n] + bhh[n];
}

// ---------------- tf32 tensor-core GEMM (128x256 tile, 64x64 warp tile, 3-stage) ----------------
#define BM 128
#define BN 256
#define BK 16
#define SL 20
#define ST_AGES 3
#define AOFF(s) ((s) * (BM * SL))
#define BOFF(s) (ST_AGES * BM * SL + (s) * (BN * SL))
#define GEMM_SMEM (ST_AGES * (BM + BN) * SL * 4)

__device__ __forceinline__ void cp16(uint32_t s, const void* g) {
    asm volatile("cp.async.cg.shared.global [%0], [%1], 16;" :: "r"(s), "l"(g));
}

template<int RA>
__global__ void __launch_bounds__(256, 1) gemm_tc(
    const float* __restrict__ A, int lda, int rowlo, int rowhi, int kvalid,
    const float* __restrict__ B, int ldb,
    const float* __restrict__ bias0, const float* __restrict__ bias1,
    float* __restrict__ C, int M, int N, int K,
    int cmode, int dorelu, int doround,
    const float* __restrict__ w2, float* __restrict__ stopP)
{
    extern __shared__ float smp[];
    __shared__ float spart[4][BM];

    const int tid  = threadIdx.x;
    const int bm   = blockIdx.x * BM;
    const int bn   = blockIdx.y * BN;
    const int warp = tid >> 5, lane = tid & 31;
    const int wm   = (warp & 1) * 64;
    const int wn   = (warp >> 1) * 64;
    const int grp  = lane >> 2;
    const int tig  = lane & 3;

    float acc[4][8][4];
#pragma unroll
    for (int i = 0; i < 4; i++)
#pragma unroll
        for (int j = 0; j < 8; j++)
#pragma unroll
            for (int e = 0; e < 4; e++) acc[i][j][e] = 0.f;

    const int T = K / BK;

#define LOAD_TILE(t)                                                            \
    {                                                                           \
        int k0 = (t) * BK;                                                      \
        int sb = (t) % ST_AGES;                                                 \
        _Pragma("unroll")                                                       \
        for (int i = 0; i < 2; i++) {                                           \
            int f = i * 256 + tid, row = f >> 2, seg = (f & 3) * 4;             \
            int ar = bm + row, kk = k0 + seg;                                   \
            float* da = smp + AOFF(sb) + row * SL + seg;                        \
            if (ar >= rowlo && ar < rowhi && kk < kvalid)                       \
                cp16((uint32_t)__cvta_generic_to_shared(da),                    \
                     A + (size_t)ar * lda + kk);                                \
            else                                                                \
                *(float4*)da = make_float4(0.f, 0.f, 0.f, 0.f);                 \
        }                                                                       \
        _Pragma("unroll")                                                       \
        for (int i = 0; i < 4; i++) {                                           \
            int f = i * 256 + tid, row = f >> 2, seg = (f & 3) * 4;             \
            float* db = smp + BOFF(sb) + row * SL + seg;                        \
            cp16((uint32_t)__cvta_generic_to_shared(db),                        \
                 B + (size_t)(bn + row) * ldb + k0 + seg);                      \
        }                                                                       \
        asm volatile("cp.async.commit_group;" ::: "memory");                    \
    }

    LOAD_TILE(0);
    LOAD_TILE(1);

    for (int t = 0; t < T; t++) {
        asm volatile("cp.async.wait_group 1;" ::: "memory");
        __syncthreads();
        if (t + 2 < T) LOAD_TILE(t + 2);

        const uint32_t* as = reinterpret_cast<const uint32_t*>(smp + AOFF(t % ST_AGES));
        const uint32_t* bs = reinterpret_cast<const uint32_t*>(smp + BOFF(t % ST_AGES));

#pragma unroll
        for (int kk = 0; kk < BK; kk += 8) {
            uint32_t a[4][4], b[8][2];
            const int c0 = kk + tig;
#pragma unroll
            for (int mt = 0; mt < 4; mt++) {
                int r0 = wm + mt * 16 + grp;
                a[mt][0] = as[r0 * SL + c0];
                a[mt][1] = as[(r0 + 8) * SL + c0];
                a[mt][2] = as[r0 * SL + c0 + 4];
                a[mt][3] = as[(r0 + 8) * SL + c0 + 4];
                if (RA) {
#pragma unroll
                    for (int q = 0; q < 4; q++)
                        a[mt][q] = __float_as_uint(to_tf32(__uint_as_float(a[mt][q])));
                }
            }
#pragma unroll
            for (int nt = 0; nt < 8; nt++) {
                int n0 = wn + nt * 8 + grp;
                b[nt][0] = bs[n0 * SL + c0];
                b[nt][1] = bs[n0 * SL + c0 + 4];
            }
#pragma unroll
            for (int mt = 0; mt < 4; mt++)
#pragma unroll
                for (int nt = 0; nt < 8; nt++) {
                    asm volatile(
                        "mma.sync.aligned.m16n8k8.row.col.f32.tf32.tf32.f32 "
                        "{%0,%1,%2,%3}, {%4,%5,%6,%7}, {%8,%9}, {%0,%1,%2,%3};"
                        : "+f"(acc[mt][nt][0]), "+f"(acc[mt][nt][1]),
                          "+f"(acc[mt][nt][2]), "+f"(acc[mt][nt][3])
                        : "r"(a[mt][0]), "r"(a[mt][1]), "r"(a[mt][2]), "r"(a[mt][3]),
                          "r"(b[nt][0]), "r"(b[nt][1]));
                }
        }
        __syncthreads();
    }
#undef LOAD_TILE

    if (cmode == 2 && bn == 256) {
        float myp[4][2];
#pragma unroll
        for (int mt = 0; mt < 4; mt++) { myp[mt][0] = 0.f; myp[mt][1] = 0.f; }
#pragma unroll
        for (int nt = 0; nt < 8; nt++)
#pragma unroll
            for (int e = 0; e < 4; e++) {
                int col = bn + wn + nt * 8 + tig * 2 + (e & 1);
                float wv = __ldg(w2 + (col - 256));
                float bv = __ldg(bias0 + col);
#pragma unroll
                for (int mt = 0; mt < 4; mt++) {
                    float v = fmaxf(acc[mt][nt][e] + bv, 0.f);
                    myp[mt][e >> 1] += v * wv;
                }
            }
#pragma unroll
        for (int mt = 0; mt < 4; mt++)
#pragma unroll
            for (int h = 0; h < 2; h++) {
                float v = myp[mt][h];
                v += __shfl_xor_sync(0xffffffffu, v, 1);
                v += __shfl_xor_sync(0xffffffffu, v, 2);
                myp[mt][h] = v;
            }
        if (tig == 0) {
            int wi = warp >> 1;
#pragma unroll
            for (int mt = 0; mt < 4; mt++)
#pragma unroll
                for (int h = 0; h < 2; h++)
                    spart[wi][wm + mt * 16 + grp + 8 * h] = myp[mt][h];
        }
        __syncthreads();
        if (tid < BM)
            stopP[bm + tid] = spart[0][tid] + spart[1][tid] + spart[2][tid] + spart[3][tid];
        return;
    }

#pragma unroll
    for (int nt = 0; nt < 8; nt++) {
#pragma unroll
        for (int e = 0; e < 4; e++) {
            int col = bn + wn + nt * 8 + tig * 2 + (e & 1);
            if (col >= N) continue;
            float bv = 0.f;
            if (bias0) bv += __ldg(bias0 + col);
            if (bias1) bv += __ldg(bias1 + col);
#pragma unroll
            for (int mt = 0; mt < 4; mt++) {
                int row = bm + wm + mt * 16 + grp + ((e >> 1) << 3);
                float v = acc[mt][nt][e] + bv;
                if (dorelu) v = fmaxf(v, 0.f);
                if (doround) v = to_tf32(v);
                if (cmode == 0)
                    C[(size_t)row * N + col] = v;
                else if (cmode == 1)
                    C[(size_t)(row >> 6) * (64 * (size_t)N) + (size_t)col * 64 + (row & 63)] = v;
                else
                    C[(size_t)row * 256 + col] = v;
            }
        }
    }
}

// ---------------- stop finalize ----------------
__global__ void stopfin_k(const float* __restrict__ b2, float* __restrict__ out) {
    int r = blockIdx.x * 256 + threadIdx.x;
    if (r < M_DEC) out[r] = g_StopP[r] + b2[0];
}

// ---------------- recurrent LSTM kernels ----------------
__device__ __forceinline__ float sigmoidf_(float x) { return 1.f / (1.f + __expf(-x)); }

__device__ __forceinline__ void bar_wait(int tid, unsigned int tgt) {
    if (tid == 0) {
        unsigned int v;
        do { asm volatile("ld.acquire.gpu.u32 %0, [%1];" : "=r"(v) : "l"(&g_bar)); }
        while (v < tgt);
    }
    __syncthreads();
}
__device__ __forceinline__ void bar_arrive(int tid) {
    __syncthreads();
    if (tid == 0)
        asm volatile("red.release.gpu.add.u32 [%0], %1;" :: "l"(&g_bar), "r"(1u) : "memory");
}

#define SEQ_NB 128
#define SEQ_NT 256

// encoder: steps 0..LT
__global__ void __launch_bounds__(SEQ_NT, 2) lstm_enc_k(
    const float* __restrict__ encWhh, const int* __restrict__ tlen)
{
    __shared__ __align__(16) float Wse[8][257];
    __shared__ __align__(16) float part[8][8][64];

    const int tid = threadIdx.x;
    const int j0 = blockIdx.x * 2;

    for (int idx = tid; idx < 8 * 256; idx += SEQ_NT) {
        int gl = idx >> 8, k = idx & 255;
        int g = gl >> 1, l = gl & 1;
        Wse[gl][k] = encWhh[(g * 256 + j0 + l) * 256 + k];
    }
    const int warp = tid >> 5, lane = tid & 31;
    const int b0  = (lane & 15) * 4;
    const int gl0 = (lane >> 4) * 4;
    const int kbeg = warp * 32;
    const int ub = tid & 63, ul = tid >> 6;
    const int uj = j0 + ul;
    const bool upd = (tid < 128);
    float c_reg = 0.f;
    const int mylen = upd ? tlen[ub] : 0;
    __syncthreads();

    for (int s = 0; s < LT; s++) {
        bar_wait(tid, (unsigned int)(SEQ_NB * s));

        const int cur = s & 1, nxt = cur ^ 1;
        const float* hb = g_hbuf + cur * (D_H * NB_);

        float gvx[4];
        if (upd) {
#pragma unroll
            for (int g = 0; g < 4; g++)
                gvx[g] = __ldcg(g_XencG + (size_t)s * (G4 * NB_) + ((g * 256 + uj) << 6) + ub);
        }

        float acc[4][4];
#pragma unroll
        for (int i = 0; i < 4; i++)
#pragma unroll
            for (int g = 0; g < 4; g++) acc[i][g] = 0.f;
#pragma unroll 8
        for (int k = kbeg; k < kbeg + 32; k++) {
            float4 h4 = __ldcg((const float4*)(hb + k * 64 + b0));
            float w0 = Wse[gl0 + 0][k], w1 = Wse[gl0 + 1][k];
            float w2 = Wse[gl0 + 2][k], w3 = Wse[gl0 + 3][k];
            acc[0][0] += h4.x * w0; acc[1][0] += h4.y * w0; acc[2][0] += h4.z * w0; acc[3][0] += h4.w * w0;
            acc[0][1] += h4.x * w1; acc[1][1] += h4.y * w1; acc[2][1] += h4.z * w1; acc[3][1] += h4.w * w1;
            acc[0][2] += h4.x * w2; acc[1][2] += h4.y * w2; acc[2][2] += h4.z * w2; acc[3][2] += h4.w * w2;
            acc[0][3] += h4.x * w3; acc[1][3] += h4.y * w3; acc[2][3] += h4.z * w3; acc[3][3] += h4.w * w3;
        }
#pragma unroll
        for (int g = 0; g < 4; g++)
            *(float4*)&part[warp][gl0 + g][b0] =
                make_float4(acc[0][g], acc[1][g], acc[2][g], acc[3][g]);
        __syncthreads();

        if (upd) {
            float gv[4];
#pragma unroll
            for (int g = 0; g < 4; g++) {
                int gl = g * 2 + ul;
                float v = gvx[g];
#pragma unroll
                for (int w = 0; w < 8; w++) v += part[w][gl][ub];
                gv[g] = v;
            }
            float iv = sigmoidf_(gv[0]);
            float fv = sigmoidf_(gv[1]);
            float gg = tanhf(gv[2]);
            float ov = sigmoidf_(gv[3]);
            float c2 = fv * c_reg + iv * gg;
            float h2 = ov * tanhf(c2);
            bool m = (s < mylen);
            float hold = __ldcg(hb + uj * 64 + ub);
            c_reg = m ? c2 : c_reg;
            float hnew = m ? h2 : hold;
            g_hbuf[nxt * (D_H * NB_) + uj * 64 + ub] = hnew;
        }
        bar_arrive(tid);
    }
}

// decoder segment: steps [s0, s1e)
__global__ void __launch_bounds__(SEQ_NT, 2) lstm_dec_k(
    const float* __restrict__ decWhh, int s0, int s1e)
{
    __shared__ __align__(16) float2 Wsd2[8][256];
    __shared__ __align__(16) float part[8][8][64];

    const int tid = threadIdx.x;
    const int j0 = blockIdx.x * 2;

    for (int idx = tid; idx < 8 * 256; idx += SEQ_NT) {
        int gl = idx >> 8, k = idx & 255;
        int g = gl >> 1, l = gl & 1;
        float wd = decWhh[(g * 256 + j0 + l) * 256 + k];
        Wsd2[gl][k] = make_float2(wd, wd);
    }
    const int warp = tid >> 5, lane = tid & 31;
    const int b0  = (lane & 15) * 4;
    const int gl0 = (lane >> 4) * 4;
    const int kbeg = warp * 32;
    const int ub = tid & 63, ul = tid >> 6;
    const int uj = j0 + ul;
    const bool upd = (tid < 128);
    float c_reg = 0.f;
    if (upd && s0 > LT) c_reg = g_cbuf[uj * 64 + ub];
    __syncthreads();

    for (int s = s0; s < s1e; s++) {
        bar_wait(tid, (unsigned int)(SEQ_NB * s));

        const int cur = s & 1, nxt = cur ^ 1;
        const float* hb = g_hbuf + cur * (D_H * NB_);
        const int t = s - LT;

        float gvx[4];
        if (upd) {
            if (t < 800) {
#pragma unroll
                for (int g = 0; g < 4; g++)
                    gvx[g] = __ldcg(g_XdG + (size_t)t * ((size_t)G4 * NB_)
                                    + ((g * 256 + uj) << 6) + ub);
            } else {
#pragma unroll
                for (int g = 0; g < 4; g++)
                    gvx[g] = __ldg(g_cvec + g * 256 + uj);
            }
        }

        unsigned long long accp[2][4];
#pragma unroll
        for (int p = 0; p < 2; p++)
#pragma unroll
            for (int g = 0; g < 4; g++) accp[p][g] = 0ull;
#pragma unroll 8
        for (int k = kbeg; k < kbeg + 32; k++) {
            ulonglong2 hq = __ldcg((const ulonglong2*)(hb + k * 64 + b0));
            unsigned long long w0 = *(const unsigned long long*)&Wsd2[gl0 + 0][k];
            unsigned long long w1 = *(const unsigned long long*)&Wsd2[gl0 + 1][k];
            unsigned long long w2 = *(const unsigned long long*)&Wsd2[gl0 + 2][k];
            unsigned long long w3 = *(const unsigned long long*)&Wsd2[gl0 + 3][k];
            asm("fma.rn.f32x2 %0, %1, %2, %0;" : "+l"(accp[0][0]) : "l"(hq.x), "l"(w0));
            asm("fma.rn.f32x2 %0, %1, %2, %0;" : "+l"(accp[1][0]) : "l"(hq.y), "l"(w0));
            asm("fma.rn.f32x2 %0, %1, %2, %0;" : "+l"(accp[0][1]) : "l"(hq.x), "l"(w1));
            asm("fma.rn.f32x2 %0, %1, %2, %0;" : "+l"(accp[1][1]) : "l"(hq.y), "l"(w1));
            asm("fma.rn.f32x2 %0, %1, %2, %0;" : "+l"(accp[0][2]) : "l"(hq.x), "l"(w2));
            asm("fma.rn.f32x2 %0, %1, %2, %0;" : "+l"(accp[1][2]) : "l"(hq.y), "l"(w2));
            asm("fma.rn.f32x2 %0, %1, %2, %0;" : "+l"(accp[0][3]) : "l"(hq.x), "l"(w3));
            asm("fma.rn.f32x2 %0, %1, %2, %0;" : "+l"(accp[1][3]) : "l"(hq.y), "l"(w3));
        }
#pragma unroll
        for (int g = 0; g < 4; g++) {
            float2 f0 = *(float2*)&accp[0][g];
            float2 f1 = *(float2*)&accp[1][g];
            *(float4*)&part[warp][gl0 + g][b0] = make_float4(f0.x, f0.y, f1.x, f1.y);
        }
        __syncthreads();

        if (upd) {
            float gv[4];
#pragma unroll
            for (int g = 0; g < 4; g++) {
                int gl = g * 2 + ul;
                float v = gvx[g];
#pragma unroll
                for (int w = 0; w < 8; w++) v += part[w][gl][ub];
                gv[g] = v;
            }
            if (s == LT)
                c_reg = __ldcg(hb + uj * 64 + ub);

            float iv = sigmoidf_(gv[0]);
            float fv = sigmoidf_(gv[1]);
            float gg = tanhf(gv[2]);
            float ov = sigmoidf_(gv[3]);
            float c2 = fv * c_reg + iv * gg;
            float h2 = ov * tanhf(c2);
            c_reg = c2;
            g_H[(size_t)t * (NB_ * D_H) + ub * D_H + uj] = to_tf32(h2);
            g_hbuf[nxt * (D_H * NB_) + uj * 64 + ub] = h2;
        }
        bar_arrive(tid);
    }
    if (upd) g_cbuf[uj * 64 + ub] = c_reg;
}

// ---------------- launch ----------------
extern "C" void kernel_launch(void* const* d_in, const int* in_sizes, int n_in,
                              void* d_out, int out_size) {
    const int*   token_pad     = (const int*)  d_in[0];
    const int*   token_lengths = (const int*)  d_in[1];
    const float* S_true        = (const float*)d_in[2];
    const float* emb           = (const float*)d_in[3];
    const float* enc_Wih       = (const float*)d_in[4];
    const float* enc_Whh       = (const float*)d_in[5];
    const float* enc_bih       = (const float*)d_in[6];
    const float* enc_bhh       = (const float*)d_in[7];
    const float* dec_Wih       = (const float*)d_in[8];
    const float* dec_Whh       = (const float*)d_in[9];
    const float* dec_bih       = (const float*)d_in[10];
    const float* dec_bhh       = (const float*)d_in[11];
    const float* pre_W         = (const float*)d_in[12];
    const float* pre_b         = (const float*)d_in[13];
    const float* post_W1       = (const float*)d_in[14];
    const float* post_b1       = (const float*)d_in[15];
    const float* post_W2       = (const float*)d_in[16];
    const float* post_b2       = (const float*)d_in[17];
    const float* stop_W1       = (const float*)d_in[18];
    const float* stop_b1       = (const float*)d_in[19];
    const float* stop_W2       = (const float*)d_in[20];
    const float* stop_b2       = (const float*)d_in[21];
    float* out = (float*)d_out;

    float *pTE, *pXencG, *pXd, *pXdG, *pH, *pHid, *pWr, *pStopP, *pBcat;
    cudaGetSymbolAddress((void**)&pTE,    g_TE);
    cudaGetSymbolAddress((void**)&pXencG, g_XencG);
    cudaGetSymbolAddress((void**)&pXd,    g_Xd);
    cudaGetSymbolAddress((void**)&pXdG,   g_XdG);
    cudaGetSymbolAddress((void**)&pH,     g_H);
    cudaGetSymbolAddress((void**)&pHid,   g_Hid);
    cudaGetSymbolAddress((void**)&pWr,    g_Wr);
    cudaGetSymbolAddress((void**)&pStopP, g_StopP);
    cudaGetSymbolAddress((void**)&pBcat,  g_bcat);

    // one-time host objects: created on the very first (correctness) call, reused by
    // every later call so graph capture allocates nothing and teardown returns to baseline
    static bool s_init = false;
    static cudaStream_t s1, s2;
    static cudaEvent_t evR, evD, evJ, evL[NSEG];
    if (!s_init) {
        s_init = true;
        cudaStreamCreateWithFlags(&s1, cudaStreamNonBlocking);
        cudaStreamCreateWithFlags(&s2, cudaStreamNonBlocking);
        cudaEventCreateWithFlags(&evR, cudaEventDisableTiming);
        cudaEventCreateWithFlags(&evD, cudaEventDisableTiming);
        cudaEventCreateWithFlags(&evJ, cudaEventDisableTiming);
        for (int i = 0; i < NSEG; i++) cudaEventCreateWithFlags(&evL[i], cudaEventDisableTiming);
        cudaFuncSetAttribute(gemm_tc<0>, cudaFuncAttributeMaxDynamicSharedMemorySize, GEMM_SMEM);
        cudaFuncSetAttribute(gemm_tc<1>, cudaFuncAttributeMaxDynamicSharedMemorySize, GEMM_SMEM);
    }

    // ---- stream 0: prep (launches 1-4) ----
    prep_k<<<(P_W2 + 255) / 256, 256>>>(enc_Wih, dec_Wih, pre_W, post_W1, stop_W1, post_W2,
                                        post_b1, stop_b1);
    gather_emb<<<M_ENC, 256>>>(token_pad, emb, pTE);
    cudaEventRecord(evR, 0);
    gemm_tc<0><<<dim3(M_ENC/128, G4/256), 256, GEMM_SMEM>>>(pTE, 256, 0, M_ENC, 256,
        pWr + W_ENC, 256, enc_bih, enc_bhh, pXencG, M_ENC, G4, 256, 1, 0, 0, nullptr, nullptr);
    lstm_enc_k<<<SEQ_NB, SEQ_NT>>>(enc_Whh, token_lengths);

    // ---- s1: pre-net (5) + dec-gate (6, ncu target) + cvec, overlapping the encoder ----
    cudaStreamWaitEvent(s1, evR, 0);
    gemm_tc<1><<<dim3(M_VAL/128, 1), 256, GEMM_SMEM, s1>>>(S_true, D_S, 64, M_VAL, D_S,
        pWr + W_PRE, KP_S, pre_b, nullptr, pXd, M_VAL, D_H, KP_S, 0, 0, 1, nullptr, nullptr);
    gemm_tc<0><<<dim3(M_VAL/128, G4/256), 256, GEMM_SMEM, s1>>>(pXd, 256, 0, M_VAL, 256,
        pWr + W_DEC, 256, dec_bih, dec_bhh, pXdG, M_VAL, G4, 256, 1, 0, 0, nullptr, nullptr);
    cvec_k<<<G4/8, 256, 0, s1>>>(pre_b, dec_bih, dec_bhh);
    cudaEventRecord(evD, s1);

    // ---- stream 0: decoder recurrence in segments ----
    cudaStreamWaitEvent(0, evD, 0);
    for (int i = 0; i < NSEG; i++) {
        lstm_dec_k<<<SEQ_NB, SEQ_NT>>>(dec_Whh, LT + i * SEG_STEPS, LT + (i + 1) * SEG_STEPS);
        cudaEventRecord(evL[i], 0);
    }

    // ---- s2: per-segment post-net chunks overlap the decoder recurrence ----
    for (int i = 0; i < NSEG; i++) {
        cudaStreamWaitEvent(s2, evL[i], 0);
        const float* Hc  = pH   + (size_t)SEG_ROWS * i * 256;
        float*       Hic = pHid + (size_t)SEG_ROWS * i * 256;
        gemm_tc<0><<<dim3(SEG_ROWS/128, 2), 256, GEMM_SMEM, s2>>>(Hc, 256, 0, SEG_ROWS, 256,
            pWr + W_P1S, 256, pBcat, nullptr, Hic, SEG_ROWS, 512, 256, 2, 1, 1,
            stop_W2, pStopP + (size_t)SEG_ROWS * i);
        gemm_tc<0><<<dim3(SEG_ROWS/128, 3), 256, GEMM_SMEM, s2>>>(Hic, 256, 0, SEG_ROWS, 256,
            pWr + W_POST2, 256, post_b2, nullptr, out + (size_t)SEG_ROWS * i * D_S,
            SEG_ROWS, D_S, 256, 0, 0, 0, nullptr, nullptr);
    }
    stopfin_k<<<(M_DEC+255)/256, 256, 0, s2>>>(stop_b2, out + STOP_OFF);
    cudaEventRecord(evJ, s2);

    // join back to stream 0
    cudaStreamWaitEvent(0, evJ, 0);
}